// round 2
// baseline (speedup 1.0000x reference)
#include <cuda_runtime.h>
#include <math.h>

#define GN   256
#define NPG  512
#define NT   (GN*NPG)
#define ET   1048576
#define SAST 130

__device__ float g_Ep[(size_t)ET*104];
__device__ float g_D [(size_t)NT*52];
__device__ float g_S [(size_t)NT*52];
__device__ float g_acc[(size_t)NT*26];
__device__ float g_h1[(size_t)NT*26];
__device__ float g_h2[(size_t)NT*26];
__device__ float g_sm[NT];
__device__ float g_c2[GN*1920];
__device__ float g_d0[GN*512];
__device__ float g_W0T[1920*512];
__device__ float g_W1T[512*256];

__device__ __forceinline__ void fma2(unsigned long long& d, unsigned long long a,
                                     unsigned long long b) {
    asm("fma.rn.f32x2 %0, %1, %2, %0;" : "+l"(d) : "l"(a), "l"(b));
}
__device__ __forceinline__ unsigned long long bcast2(float w) {
    unsigned long long r; unsigned wi = __float_as_uint(w);
    asm("mov.b64 %0, {%1, %1};" : "=l"(r) : "r"(wi));
    return r;
}

// ---- Eproj GEMM: [E,52] @ Wcomb^T -> [E,104], rows = [f1|s1|f2|s2] edge parts
__global__ __launch_bounds__(128) void k_eproj(const float* __restrict__ ea,
        const float* __restrict__ Wf1, const float* __restrict__ Ws1,
        const float* __restrict__ Wf2, const float* __restrict__ Ws2) {
    __shared__ __align__(16) float sA[52*SAST];
    __shared__ __align__(16) float sW[52*104];
    int tid = threadIdx.x, eb = blockIdx.x * 128;
    for (int i = tid; i < 128*52; i += 128) {
        int e = i / 52, k = i - e*52;
        sA[k*SAST + e] = ea[(size_t)(eb + e)*52 + k];
    }
    for (int i = tid; i < 52*104; i += 128) {
        int k = i / 104, o = i - k*104;
        const float* W; int r;
        if      (o < 26) { W = Wf1; r = o;      }
        else if (o < 52) { W = Ws1; r = o - 26; }
        else if (o < 78) { W = Wf2; r = o - 52; }
        else             { W = Ws2; r = o - 78; }
        sW[i] = W[r*104 + 52 + k];
    }
    __syncthreads();
    int og = tid & 7, eg = tid >> 3;
    int o0 = og * 13, e0 = eg * 8;
    unsigned long long acc[4][13];
    #pragma unroll
    for (int p = 0; p < 4; p++)
        #pragma unroll
        for (int j = 0; j < 13; j++) acc[p][j] = 0ull;
    #pragma unroll 4
    for (int k = 0; k < 52; k++) {
        const unsigned long long* ap =
            reinterpret_cast<const unsigned long long*>(sA + k*SAST + e0);
        unsigned long long a0 = ap[0], a1 = ap[1], a2 = ap[2], a3 = ap[3];
        #pragma unroll
        for (int j = 0; j < 13; j++) {
            unsigned long long w2 = bcast2(sW[k*104 + o0 + j]);
            fma2(acc[0][j], a0, w2); fma2(acc[1][j], a1, w2);
            fma2(acc[2][j], a2, w2); fma2(acc[3][j], a3, w2);
        }
    }
    #pragma unroll
    for (int p = 0; p < 4; p++) {
        int e = eb + e0 + 2*p;
        #pragma unroll
        for (int j = 0; j < 13; j++) {
            float2 v = *reinterpret_cast<float2*>(&acc[p][j]);
            g_Ep[(size_t)e*104 + o0 + j]       = v.x;
            g_Ep[(size_t)(e + 1)*104 + o0 + j] = v.y;
        }
    }
}

// ---- per-node dst/src gate terms, bias folded into D; zero accumulator
__global__ __launch_bounds__(256) void k_nodeproj(const float* __restrict__ xin,
        int layer, const float* __restrict__ Wf, const float* __restrict__ Ws,
        const float* __restrict__ bf, const float* __restrict__ bs) {
    __shared__ __align__(16) float sWd[52*28];
    __shared__ __align__(16) float sWs[52*28];
    __shared__ float sbias[52];
    int tid = threadIdx.x;
    for (int i = tid; i < 52*26; i += 256) {
        int r = i / 26, k = i - r*26;
        const float* W = (r < 26) ? Wf : Ws;
        int rr = (r < 26) ? r : r - 26;
        sWd[r*28 + k] = W[rr*104 + k];
        sWs[r*28 + k] = W[rr*104 + 26 + k];
    }
    if (tid < 52) sbias[tid] = (tid < 26) ? bf[tid] : bs[tid - 26];
    __syncthreads();
    const float* h = layer ? g_h1 : xin;
    int n = blockIdx.x*256 + tid;
    float hr[26];
    const float2* hp = reinterpret_cast<const float2*>(h + (size_t)n*26);
    #pragma unroll
    for (int q = 0; q < 13; q++) { float2 v = hp[q]; hr[2*q] = v.x; hr[2*q+1] = v.y; }
    float* Dp = g_D + (size_t)n*52;
    float* Sp = g_S + (size_t)n*52;
    #pragma unroll 4
    for (int r = 0; r < 52; r++) {
        float ad = sbias[r], as = 0.f;
        const float4* wd = reinterpret_cast<const float4*>(sWd + r*28);
        const float4* ws = reinterpret_cast<const float4*>(sWs + r*28);
        #pragma unroll
        for (int q = 0; q < 6; q++) {
            float4 a = wd[q], b = ws[q];
            ad += a.x*hr[4*q] + a.y*hr[4*q+1] + a.z*hr[4*q+2] + a.w*hr[4*q+3];
            as += b.x*hr[4*q] + b.y*hr[4*q+1] + b.z*hr[4*q+2] + b.w*hr[4*q+3];
        }
        ad += sWd[r*28+24]*hr[24] + sWd[r*28+25]*hr[25];
        as += sWs[r*28+24]*hr[24] + sWs[r*28+25]*hr[25];
        Dp[r] = ad; Sp[r] = as;
    }
    float* ap = g_acc + (size_t)n*26;
    #pragma unroll
    for (int j = 0; j < 26; j++) ap[j] = 0.f;
}

// ---- per-edge gate + message + scatter-add
__global__ __launch_bounds__(256) void k_edge(const int* __restrict__ ei, int layerOff) {
    int e = blockIdx.x*256 + threadIdx.x;
    int s = ei[e], d = ei[ET + e];
    const float* Dp = g_D + (size_t)d*52;
    const float* Sp = g_S + (size_t)s*52;
    const float* Eb = g_Ep + (size_t)e*104 + layerOff;
    float* ap = g_acc + (size_t)d*26;
    #pragma unroll
    for (int o = 0; o < 26; o += 2) {
        float2 dl = *reinterpret_cast<const float2*>(Dp + o);
        float2 dh = *reinterpret_cast<const float2*>(Dp + 26 + o);
        float2 sl = *reinterpret_cast<const float2*>(Sp + o);
        float2 sh = *reinterpret_cast<const float2*>(Sp + 26 + o);
        float2 el = __ldcs(reinterpret_cast<const float2*>(Eb + o));
        float2 eh = __ldcs(reinterpret_cast<const float2*>(Eb + 26 + o));
        float gf0 = dl.x + sl.x + el.x, gf1 = dl.y + sl.y + el.y;
        float gs0 = dh.x + sh.x + eh.x, gs1 = dh.y + sh.y + eh.y;
        float sg0 = 1.f / (1.f + __expf(-gf0));
        float sg1 = 1.f / (1.f + __expf(-gf1));
        float sp0 = (gs0 > 20.f) ? gs0 : __logf(1.f + __expf(gs0));
        float sp1 = (gs1 > 20.f) ? gs1 : __logf(1.f + __expf(gs1));
        atomicAdd(ap + o,     sg0*sp0);
        atomicAdd(ap + o + 1, sg1*sp1);
    }
}

__global__ void k_finalize(const float* __restrict__ xin, int layer) {
    int i = blockIdx.x*256 + threadIdx.x;
    if (layer == 0) g_h1[i] = tanhf(xin[i] + g_acc[i]);
    else            g_h2[i] = tanhf(g_h1[i] + g_acc[i]);
}

__global__ __launch_bounds__(256) void k_softmax(const float* __restrict__ ic) {
    __shared__ float red[256];
    int g = blockIdx.x, t = threadIdx.x;
    size_t base = (size_t)g * NPG;
    float v0 = ic[base + t], v1 = ic[base + 256 + t];
    red[t] = fmaxf(v0, v1); __syncthreads();
    for (int st = 128; st > 0; st >>= 1) {
        if (t < st) red[t] = fmaxf(red[t], red[t + st]);
        __syncthreads();
    }
    float m = red[0]; __syncthreads();
    float e0 = __expf(v0 - m), e1 = __expf(v1 - m);
    red[t] = e0 + e1; __syncthreads();
    for (int st = 128; st > 0; st >>= 1) {
        if (t < st) red[t] += red[t + st];
        __syncthreads();
    }
    float inv = 1.f / red[0];
    g_sm[base + t] = e0 * inv;
    g_sm[base + 256 + t] = e1 * inv;
}

// ---- per-graph: bitonic sort-pool + conv1 + maxpool + conv2
__global__ __launch_bounds__(256) void k_sortpool(const float* __restrict__ Wc1,
        const float* __restrict__ bc1, const float* __restrict__ Wc2,
        const float* __restrict__ bc2) {
    __shared__ float sv[512];
    __shared__ unsigned short si[512];
    __shared__ float pf[128*53];
    __shared__ float m16[16*64];
    __shared__ float swc1[16*53];
    __shared__ float swc2[2560];
    __shared__ float sb1[16], sb2[32];
    int g = blockIdx.x, t = threadIdx.x;
    size_t nb = (size_t)g * NPG;
    sv[t] = g_sm[nb + t];           si[t] = (unsigned short)t;
    sv[t+256] = g_sm[nb + 256 + t]; si[t+256] = (unsigned short)(t + 256);
    for (int i = t; i < 16*53; i += 256) swc1[i] = Wc1[i];
    for (int i = t; i < 2560;  i += 256) swc2[i] = Wc2[i];
    if (t < 16) sb1[t] = bc1[t];
    if (t < 32) sb2[t] = bc2[t];
    __syncthreads();
    // descending by value, ties -> smaller index (stable argsort(-v))
    for (int size = 2; size <= 512; size <<= 1) {
        for (int stride = size >> 1; stride > 0; stride >>= 1) {
            int q = t / stride, r = t - q*stride;
            int i = q*2*stride + r, j = i + stride;
            bool dir = ((i & size) == 0);
            float av = sv[i], bv = sv[j];
            int ai = si[i], bi = si[j];
            bool before = (av > bv) || (av == bv && ai < bi);
            if (dir ? !before : before) {
                sv[i] = bv; sv[j] = av;
                si[i] = (unsigned short)bi; si[j] = (unsigned short)ai;
            }
            __syncthreads();
        }
    }
    for (int i = t; i < 128*53; i += 256) {
        int k = i / 53, l = i - k*53;
        int node = (int)nb + (int)si[k];
        float v;
        if (l < 26)      v = g_h1[(size_t)node*26 + l];
        else if (l < 52) v = g_h2[(size_t)node*26 + l - 26];
        else             v = sv[k];
        pf[i] = v;
    }
    __syncthreads();
    for (int task = t; task < 1024; task += 256) {
        int c = task & 15, j = task >> 4;
        const float* w  = swc1 + c*53;
        const float* p0 = pf + (2*j)*53;
        const float* p1 = p0 + 53;
        float a = sb1[c], b = sb1[c];
        #pragma unroll 13
        for (int l = 0; l < 53; l++) { a += w[l]*p0[l]; b += w[l]*p1[l]; }
        a = fmaxf(a, 0.f); b = fmaxf(b, 0.f);
        m16[c*64 + j] = fmaxf(a, b);
    }
    __syncthreads();
    for (int task = t; task < 1920; task += 256) {
        int oc = task / 60, p = task - oc*60;
        float acc = sb2[oc];
        #pragma unroll 4
        for (int ic2 = 0; ic2 < 16; ic2++) {
            const float* w  = swc2 + (oc*16 + ic2)*5;
            const float* mm = m16 + ic2*64 + p;
            #pragma unroll
            for (int u = 0; u < 5; u++) acc += w[u]*mm[u];
        }
        g_c2[g*1920 + task] = fmaxf(acc, 0.f);
    }
}

__global__ void k_transW0(const float* __restrict__ W0) {
    int i = blockIdx.x*256 + threadIdx.x;
    int k = i >> 9, o = i & 511;
    g_W0T[i] = W0[o*1920 + k];
}
__global__ void k_transW1(const float* __restrict__ W1) {
    int i = blockIdx.x*256 + threadIdx.x;
    int k = i >> 8, o = i & 255;
    g_W1T[i] = W1[o*512 + k];
}

__global__ __launch_bounds__(256) void k_dense0(const float* __restrict__ b0) {
    __shared__ float sA[4*1920];
    int t = threadIdx.x, gb = blockIdx.x*4;
    for (int i = t; i < 4*1920; i += 256) sA[i] = g_c2[gb*1920 + i];
    __syncthreads();
    float bb0 = b0[t], bb1 = b0[t + 256];
    float acc0[4], acc1[4];
    #pragma unroll
    for (int g2 = 0; g2 < 4; g2++) { acc0[g2] = bb0; acc1[g2] = bb1; }
    for (int k = 0; k < 1920; k++) {
        float w0 = g_W0T[k*512 + t];
        float w1 = g_W0T[k*512 + t + 256];
        #pragma unroll
        for (int g2 = 0; g2 < 4; g2++) {
            float a = sA[g2*1920 + k];
            acc0[g2] += a*w0; acc1[g2] += a*w1;
        }
    }
    #pragma unroll
    for (int g2 = 0; g2 < 4; g2++) {
        g_d0[(gb + g2)*512 + t]       = fmaxf(acc0[g2], 0.f);
        g_d0[(gb + g2)*512 + t + 256] = fmaxf(acc1[g2], 0.f);
    }
}

__global__ __launch_bounds__(256) void k_dense12(const float* __restrict__ b1,
        const float* __restrict__ W2, const float* __restrict__ b2,
        float* __restrict__ out) {
    __shared__ float sd[512];
    __shared__ float red[256];
    int g = blockIdx.x, t = threadIdx.x;
    sd[t] = g_d0[g*512 + t]; sd[t+256] = g_d0[g*512 + 256 + t];
    __syncthreads();
    float acc = b1[t];
    #pragma unroll 8
    for (int k = 0; k < 512; k++) acc += sd[k] * g_W1T[k*256 + t];
    red[t] = fmaxf(acc, 0.f) * W2[t];
    __syncthreads();
    for (int st = 128; st > 0; st >>= 1) {
        if (t < st) red[t] += red[t + st];
        __syncthreads();
    }
    if (t == 0) out[g] = red[0] + b2[0];
}

extern "C" void kernel_launch(void* const* d_in, const int* in_sizes, int n_in,
                              void* d_out, int out_size) {
    const float* x   = (const float*)d_in[0];
    const float* ea  = (const float*)d_in[1];
    const float* ic  = (const float*)d_in[2];
    const float* Wf1 = (const float*)d_in[3];
    const float* bf1 = (const float*)d_in[4];
    const float* Ws1 = (const float*)d_in[5];
    const float* bs1 = (const float*)d_in[6];
    const float* Wf2 = (const float*)d_in[7];
    const float* bf2 = (const float*)d_in[8];
    const float* Ws2 = (const float*)d_in[9];
    const float* bs2 = (const float*)d_in[10];
    const float* Wc1 = (const float*)d_in[11];
    const float* bc1 = (const float*)d_in[12];
    const float* Wc2 = (const float*)d_in[13];
    const float* bc2 = (const float*)d_in[14];
    const float* W0  = (const float*)d_in[15];
    const float* b0  = (const float*)d_in[16];
    const float* W1  = (const float*)d_in[17];
    const float* b1  = (const float*)d_in[18];
    const float* W2  = (const float*)d_in[19];
    const float* b2  = (const float*)d_in[20];
    const int*   ei  = (const int*)d_in[21];
    float* out = (float*)d_out;

    k_transW0<<<3840, 256>>>(W0);
    k_transW1<<<512, 256>>>(W1);
    k_eproj<<<ET/128, 128>>>(ea, Wf1, Ws1, Wf2, Ws2);

    k_nodeproj<<<NT/256, 256>>>(x, 0, Wf1, Ws1, bf1, bs1);
    k_edge<<<ET/256, 256>>>(ei, 0);
    k_finalize<<<NT*26/256, 256>>>(x, 0);

    k_nodeproj<<<NT/256, 256>>>(x, 1, Wf2, Ws2, bf2, bs2);
    k_edge<<<ET/256, 256>>>(ei, 52);
    k_finalize<<<NT*26/256, 256>>>(x, 1);

    k_softmax<<<GN, 256>>>(ic);
    k_sortpool<<<GN, 256>>>(Wc1, bc1, Wc2, bc2);
    k_dense0<<<GN/4, 256>>>(b0);
    k_dense12<<<GN, 256>>>(b1, W2, b2, out);
}

// round 3
// speedup vs baseline: 1.1739x; 1.1739x over previous
#include <cuda_runtime.h>
#include <math.h>

#define GN   256
#define NPG  512
#define NT   (GN*NPG)
#define ET   1048576
#define SAST 130

// padded layouts for 16B-aligned vector ops
#define DST  56      // g_D/g_S row stride: [f 0..25 | pad | s 28..53 | pad]
#define EPST 112     // g_Ep row: [L1f 0..25|pad|L1s 28..53|pad|L2f 56..81|pad|L2s 84..109|pad]
#define ACST 28      // g_acc row stride

__device__ float g_Ep[(size_t)ET*EPST];
__device__ float g_D [(size_t)NT*DST];
__device__ float g_S [(size_t)NT*DST];
__device__ float g_acc[(size_t)NT*ACST];
__device__ float g_h1[(size_t)NT*26];
__device__ float g_h2[(size_t)NT*26];
__device__ float g_sm[NT];
__device__ float g_c2[GN*1920];
__device__ float g_d0[GN*512];
__device__ float g_W0T[1920*512];
__device__ float g_W1T[512*256];

__device__ __forceinline__ void fma2(unsigned long long& d, unsigned long long a,
                                     unsigned long long b) {
    asm("fma.rn.f32x2 %0, %1, %2, %0;" : "+l"(d) : "l"(a), "l"(b));
}
__device__ __forceinline__ unsigned long long bcast2(float w) {
    unsigned long long r; unsigned wi = __float_as_uint(w);
    asm("mov.b64 %0, {%1, %1};" : "=l"(r) : "r"(wi));
    return r;
}
__device__ __forceinline__ void redv4(float* p, float a, float b, float c, float d) {
    asm volatile("red.global.add.v4.f32 [%0], {%1,%2,%3,%4};"
                 :: "l"(p), "f"(a), "f"(b), "f"(c), "f"(d) : "memory");
}
__device__ __forceinline__ void redv2(float* p, float a, float b) {
    asm volatile("red.global.add.v2.f32 [%0], {%1,%2};"
                 :: "l"(p), "f"(a), "f"(b) : "memory");
}

// ---- Eproj GEMM: [E,52] @ Wcomb^T -> padded [E,112]
__global__ __launch_bounds__(128) void k_eproj(const float* __restrict__ ea,
        const float* __restrict__ Wf1, const float* __restrict__ Ws1,
        const float* __restrict__ Wf2, const float* __restrict__ Ws2) {
    __shared__ __align__(16) float sA[52*SAST];
    __shared__ __align__(16) float sW[52*104];
    int tid = threadIdx.x, eb = blockIdx.x * 128;
    for (int i = tid; i < 128*52; i += 128) {
        int e = i / 52, k = i - e*52;
        sA[k*SAST + e] = ea[(size_t)(eb + e)*52 + k];
    }
    for (int i = tid; i < 52*104; i += 128) {
        int k = i / 104, o = i - k*104;
        const float* W; int r;
        if      (o < 26) { W = Wf1; r = o;      }
        else if (o < 52) { W = Ws1; r = o - 26; }
        else if (o < 78) { W = Wf2; r = o - 52; }
        else             { W = Ws2; r = o - 78; }
        sW[i] = W[r*104 + 52 + k];
    }
    __syncthreads();
    int og = tid & 7, eg = tid >> 3;
    int o0 = og * 13, e0 = eg * 8;
    unsigned long long acc[4][13];
    #pragma unroll
    for (int p = 0; p < 4; p++)
        #pragma unroll
        for (int j = 0; j < 13; j++) acc[p][j] = 0ull;
    #pragma unroll 4
    for (int k = 0; k < 52; k++) {
        const unsigned long long* ap =
            reinterpret_cast<const unsigned long long*>(sA + k*SAST + e0);
        unsigned long long a0 = ap[0], a1 = ap[1], a2 = ap[2], a3 = ap[3];
        #pragma unroll
        for (int j = 0; j < 13; j++) {
            unsigned long long w2 = bcast2(sW[k*104 + o0 + j]);
            fma2(acc[0][j], a0, w2); fma2(acc[1][j], a1, w2);
            fma2(acc[2][j], a2, w2); fma2(acc[3][j], a3, w2);
        }
    }
    #pragma unroll
    for (int p = 0; p < 4; p++) {
        int e = eb + e0 + 2*p;
        #pragma unroll
        for (int j = 0; j < 13; j++) {
            int oo = o0 + j;
            int off = (oo / 26) * 28 + (oo % 26);
            float2 v = *reinterpret_cast<float2*>(&acc[p][j]);
            g_Ep[(size_t)e*EPST + off]       = v.x;
            g_Ep[(size_t)(e + 1)*EPST + off] = v.y;
        }
    }
}

// ---- node gate terms as GEMM: [NT,26] @ [104,26]^T, f32x2 tiled; zero acc
__global__ __launch_bounds__(128) void k_nodeproj(const float* __restrict__ xin,
        int layer, const float* __restrict__ Wf, const float* __restrict__ Ws,
        const float* __restrict__ bf, const float* __restrict__ bs) {
    __shared__ __align__(16) float sA[26*SAST];
    __shared__ __align__(16) float sW[26*104];
    __shared__ float sbias[104];
    int tid = threadIdx.x, nb = blockIdx.x * 128;
    const float* h = layer ? g_h1 : xin;
    for (int i = tid; i < 128*26; i += 128) {
        int n = i / 26, k = i - n*26;
        sA[k*SAST + n] = h[(size_t)(nb + n)*26 + k];
    }
    // rows 0..25: Wf dst-cols, 26..51: Ws dst-cols, 52..77: Wf src-cols, 78..103: Ws src-cols
    for (int i = tid; i < 26*104; i += 128) {
        int k = i / 104, o = i - k*104;
        int half = (o < 52) ? 0 : 26;          // dst cols 0..25, src cols 26..51
        int oo = (o < 52) ? o : o - 52;
        const float* W = (oo < 26) ? Wf : Ws;
        int r = (oo < 26) ? oo : oo - 26;
        sW[i] = W[r*104 + half + k];
    }
    if (tid < 104) sbias[tid] = (tid < 26) ? bf[tid] : (tid < 52 ? bs[tid-26] : 0.f);
    __syncthreads();
    int og = tid & 7, eg = tid >> 3;
    int o0 = og * 13, n0 = eg * 8;
    unsigned long long acc[4][13];
    #pragma unroll
    for (int p = 0; p < 4; p++)
        #pragma unroll
        for (int j = 0; j < 13; j++) acc[p][j] = 0ull;
    #pragma unroll 2
    for (int k = 0; k < 26; k++) {
        const unsigned long long* ap =
            reinterpret_cast<const unsigned long long*>(sA + k*SAST + n0);
        unsigned long long a0 = ap[0], a1 = ap[1], a2 = ap[2], a3 = ap[3];
        #pragma unroll
        for (int j = 0; j < 13; j++) {
            unsigned long long w2 = bcast2(sW[k*104 + o0 + j]);
            fma2(acc[0][j], a0, w2); fma2(acc[1][j], a1, w2);
            fma2(acc[2][j], a2, w2); fma2(acc[3][j], a3, w2);
        }
    }
    #pragma unroll
    for (int p = 0; p < 4; p++) {
        int n = nb + n0 + 2*p;
        #pragma unroll
        for (int j = 0; j < 13; j++) {
            int oo = o0 + j;
            float bv = sbias[oo];
            int src = (oo >= 52);
            int ol = src ? oo - 52 : oo;       // 0..51 within D or S
            int off = (ol / 26) * 28 + (ol % 26);
            float* B = src ? g_S : g_D;
            float2 v = *reinterpret_cast<float2*>(&acc[p][j]);
            B[(size_t)n*DST + off]       = v.x + bv;
            B[(size_t)(n + 1)*DST + off] = v.y + bv;
        }
    }
    // zero accumulator rows for this block's nodes (1 thread = 1 node)
    float4 z = make_float4(0.f, 0.f, 0.f, 0.f);
    float4* zp = reinterpret_cast<float4*>(g_acc + (size_t)(nb + tid)*ACST);
    #pragma unroll
    for (int q = 0; q < 7; q++) zp[q] = z;
}

// ---- per-edge gate + message + vector scatter-add
__global__ __launch_bounds__(256) void k_edge(const int* __restrict__ ei, int layerOff) {
    int e = blockIdx.x*256 + threadIdx.x;
    int s = ei[e], d = ei[ET + e];
    const float* Dp = g_D + (size_t)d*DST;
    const float* Sp = g_S + (size_t)s*DST;
    const float* Eb = g_Ep + (size_t)e*EPST + layerOff;
    float* ap = g_acc + (size_t)d*ACST;
    #pragma unroll
    for (int o = 0; o < 24; o += 4) {
        float4 df = *reinterpret_cast<const float4*>(Dp + o);
        float4 ds = *reinterpret_cast<const float4*>(Dp + 28 + o);
        float4 sf = *reinterpret_cast<const float4*>(Sp + o);
        float4 ss = *reinterpret_cast<const float4*>(Sp + 28 + o);
        float4 ef = __ldcs(reinterpret_cast<const float4*>(Eb + o));
        float4 es = __ldcs(reinterpret_cast<const float4*>(Eb + 28 + o));
        float f0 = df.x+sf.x+ef.x, f1 = df.y+sf.y+ef.y;
        float f2 = df.z+sf.z+ef.z, f3 = df.w+sf.w+ef.w;
        float g0 = ds.x+ss.x+es.x, g1 = ds.y+ss.y+es.y;
        float g2 = ds.z+ss.z+es.z, g3 = ds.w+ss.w+es.w;
        float m0 = (1.f/(1.f+__expf(-f0))) * ((g0>20.f)?g0:__logf(1.f+__expf(g0)));
        float m1 = (1.f/(1.f+__expf(-f1))) * ((g1>20.f)?g1:__logf(1.f+__expf(g1)));
        float m2 = (1.f/(1.f+__expf(-f2))) * ((g2>20.f)?g2:__logf(1.f+__expf(g2)));
        float m3 = (1.f/(1.f+__expf(-f3))) * ((g3>20.f)?g3:__logf(1.f+__expf(g3)));
        redv4(ap + o, m0, m1, m2, m3);
    }
    {
        float2 df = *reinterpret_cast<const float2*>(Dp + 24);
        float2 ds = *reinterpret_cast<const float2*>(Dp + 28 + 24);
        float2 sf = *reinterpret_cast<const float2*>(Sp + 24);
        float2 ss = *reinterpret_cast<const float2*>(Sp + 28 + 24);
        float2 ef = __ldcs(reinterpret_cast<const float2*>(Eb + 24));
        float2 es = __ldcs(reinterpret_cast<const float2*>(Eb + 28 + 24));
        float f0 = df.x+sf.x+ef.x, f1 = df.y+sf.y+ef.y;
        float g0 = ds.x+ss.x+es.x, g1 = ds.y+ss.y+es.y;
        float m0 = (1.f/(1.f+__expf(-f0))) * ((g0>20.f)?g0:__logf(1.f+__expf(g0)));
        float m1 = (1.f/(1.f+__expf(-f1))) * ((g1>20.f)?g1:__logf(1.f+__expf(g1)));
        redv2(ap + 24, m0, m1);
    }
}

__global__ void k_finalize(const float* __restrict__ xin, int layer) {
    int n = blockIdx.x*256 + threadIdx.x;
    const float* prev = layer ? g_h1 : xin;
    float* outp = layer ? g_h2 : g_h1;
    const float* ac = g_acc + (size_t)n*ACST;
    #pragma unroll
    for (int j = 0; j < 26; j++)
        outp[(size_t)n*26 + j] = tanhf(prev[(size_t)n*26 + j] + ac[j]);
}

__global__ __launch_bounds__(256) void k_softmax(const float* __restrict__ ic) {
    __shared__ float red[256];
    int g = blockIdx.x, t = threadIdx.x;
    size_t base = (size_t)g * NPG;
    float v0 = ic[base + t], v1 = ic[base + 256 + t];
    red[t] = fmaxf(v0, v1); __syncthreads();
    for (int st = 128; st > 0; st >>= 1) {
        if (t < st) red[t] = fmaxf(red[t], red[t + st]);
        __syncthreads();
    }
    float m = red[0]; __syncthreads();
    float e0 = __expf(v0 - m), e1 = __expf(v1 - m);
    red[t] = e0 + e1; __syncthreads();
    for (int st = 128; st > 0; st >>= 1) {
        if (t < st) red[t] += red[t + st];
        __syncthreads();
    }
    float inv = 1.f / red[0];
    g_sm[base + t] = e0 * inv;
    g_sm[base + 256 + t] = e1 * inv;
}

__global__ __launch_bounds__(256) void k_sortpool(const float* __restrict__ Wc1,
        const float* __restrict__ bc1, const float* __restrict__ Wc2,
        const float* __restrict__ bc2) {
    __shared__ float sv[512];
    __shared__ unsigned short si[512];
    __shared__ float pf[128*53];
    __shared__ float m16[16*64];
    __shared__ float swc1[16*53];
    __shared__ float swc2[2560];
    __shared__ float sb1[16], sb2[32];
    int g = blockIdx.x, t = threadIdx.x;
    size_t nb = (size_t)g * NPG;
    sv[t] = g_sm[nb + t];           si[t] = (unsigned short)t;
    sv[t+256] = g_sm[nb + 256 + t]; si[t+256] = (unsigned short)(t + 256);
    for (int i = t; i < 16*53; i += 256) swc1[i] = Wc1[i];
    for (int i = t; i < 2560;  i += 256) swc2[i] = Wc2[i];
    if (t < 16) sb1[t] = bc1[t];
    if (t < 32) sb2[t] = bc2[t];
    __syncthreads();
    for (int size = 2; size <= 512; size <<= 1) {
        for (int stride = size >> 1; stride > 0; stride >>= 1) {
            int q = t / stride, r = t - q*stride;
            int i = q*2*stride + r, j = i + stride;
            bool dir = ((i & size) == 0);
            float av = sv[i], bv = sv[j];
            int ai = si[i], bi = si[j];
            bool before = (av > bv) || (av == bv && ai < bi);
            if (dir ? !before : before) {
                sv[i] = bv; sv[j] = av;
                si[i] = (unsigned short)bi; si[j] = (unsigned short)ai;
            }
            __syncthreads();
        }
    }
    for (int i = t; i < 128*53; i += 256) {
        int k = i / 53, l = i - k*53;
        int node = (int)nb + (int)si[k];
        float v;
        if (l < 26)      v = g_h1[(size_t)node*26 + l];
        else if (l < 52) v = g_h2[(size_t)node*26 + l - 26];
        else             v = sv[k];
        pf[i] = v;
    }
    __syncthreads();
    for (int task = t; task < 1024; task += 256) {
        int c = task & 15, j = task >> 4;
        const float* w  = swc1 + c*53;
        const float* p0 = pf + (2*j)*53;
        const float* p1 = p0 + 53;
        float a = sb1[c], b = sb1[c];
        #pragma unroll 13
        for (int l = 0; l < 53; l++) { a += w[l]*p0[l]; b += w[l]*p1[l]; }
        a = fmaxf(a, 0.f); b = fmaxf(b, 0.f);
        m16[c*64 + j] = fmaxf(a, b);
    }
    __syncthreads();
    for (int task = t; task < 1920; task += 256) {
        int oc = task / 60, p = task - oc*60;
        float acc = sb2[oc];
        #pragma unroll 4
        for (int ic2 = 0; ic2 < 16; ic2++) {
            const float* w  = swc2 + (oc*16 + ic2)*5;
            const float* mm = m16 + ic2*64 + p;
            #pragma unroll
            for (int u = 0; u < 5; u++) acc += w[u]*mm[u];
        }
        g_c2[g*1920 + task] = fmaxf(acc, 0.f);
    }
}

__global__ void k_transW0(const float* __restrict__ W0) {
    int i = blockIdx.x*256 + threadIdx.x;
    int k = i >> 9, o = i & 511;
    g_W0T[i] = W0[o*1920 + k];
}
__global__ void k_transW1(const float* __restrict__ W1) {
    int i = blockIdx.x*256 + threadIdx.x;
    int k = i >> 8, o = i & 255;
    g_W1T[i] = W1[o*512 + k];
}

__global__ __launch_bounds__(256) void k_dense0(const float* __restrict__ b0) {
    __shared__ float sA[4*1920];
    int t = threadIdx.x, gb = blockIdx.x*4;
    for (int i = t; i < 4*1920; i += 256) sA[i] = g_c2[gb*1920 + i];
    __syncthreads();
    float bb0 = b0[t], bb1 = b0[t + 256];
    float acc0[4], acc1[4];
    #pragma unroll
    for (int g2 = 0; g2 < 4; g2++) { acc0[g2] = bb0; acc1[g2] = bb1; }
    for (int k = 0; k < 1920; k++) {
        float w0 = g_W0T[k*512 + t];
        float w1 = g_W0T[k*512 + t + 256];
        #pragma unroll
        for (int g2 = 0; g2 < 4; g2++) {
            float a = sA[g2*1920 + k];
            acc0[g2] += a*w0; acc1[g2] += a*w1;
        }
    }
    #pragma unroll
    for (int g2 = 0; g2 < 4; g2++) {
        g_d0[(gb + g2)*512 + t]       = fmaxf(acc0[g2], 0.f);
        g_d0[(gb + g2)*512 + t + 256] = fmaxf(acc1[g2], 0.f);
    }
}

__global__ __launch_bounds__(256) void k_dense12(const float* __restrict__ b1,
        const float* __restrict__ W2, const float* __restrict__ b2,
        float* __restrict__ out) {
    __shared__ float sd[512];
    __shared__ float red[256];
    int g = blockIdx.x, t = threadIdx.x;
    sd[t] = g_d0[g*512 + t]; sd[t+256] = g_d0[g*512 + 256 + t];
    __syncthreads();
    float acc = b1[t];
    #pragma unroll 8
    for (int k = 0; k < 512; k++) acc += sd[k] * g_W1T[k*256 + t];
    red[t] = fmaxf(acc, 0.f) * W2[t];
    __syncthreads();
    for (int st = 128; st > 0; st >>= 1) {
        if (t < st) red[t] += red[t + st];
        __syncthreads();
    }
    if (t == 0) out[g] = red[0] + b2[0];
}

extern "C" void kernel_launch(void* const* d_in, const int* in_sizes, int n_in,
                              void* d_out, int out_size) {
    const float* x   = (const float*)d_in[0];
    const float* ea  = (const float*)d_in[1];
    const float* ic  = (const float*)d_in[2];
    const float* Wf1 = (const float*)d_in[3];
    const float* bf1 = (const float*)d_in[4];
    const float* Ws1 = (const float*)d_in[5];
    const float* bs1 = (const float*)d_in[6];
    const float* Wf2 = (const float*)d_in[7];
    const float* bf2 = (const float*)d_in[8];
    const float* Ws2 = (const float*)d_in[9];
    const float* bs2 = (const float*)d_in[10];
    const float* Wc1 = (const float*)d_in[11];
    const float* bc1 = (const float*)d_in[12];
    const float* Wc2 = (const float*)d_in[13];
    const float* bc2 = (const float*)d_in[14];
    const float* W0  = (const float*)d_in[15];
    const float* b0  = (const float*)d_in[16];
    const float* W1  = (const float*)d_in[17];
    const float* b1  = (const float*)d_in[18];
    const float* W2  = (const float*)d_in[19];
    const float* b2  = (const float*)d_in[20];
    const int*   ei  = (const int*)d_in[21];
    float* out = (float*)d_out;

    k_transW0<<<3840, 256>>>(W0);
    k_transW1<<<512, 256>>>(W1);
    k_eproj<<<ET/128, 128>>>(ea, Wf1, Ws1, Wf2, Ws2);

    k_nodeproj<<<NT/128, 128>>>(x, 0, Wf1, Ws1, bf1, bs1);
    k_edge<<<ET/256, 256>>>(ei, 0);
    k_finalize<<<NT/256, 256>>>(x, 0);

    k_nodeproj<<<NT/128, 128>>>(x, 1, Wf2, Ws2, bf2, bs2);
    k_edge<<<ET/256, 256>>>(ei, 56);
    k_finalize<<<NT/256, 256>>>(x, 1);

    k_softmax<<<GN, 256>>>(ic);
    k_sortpool<<<GN, 256>>>(Wc1, bc1, Wc2, bc2);
    k_dense0<<<GN/4, 256>>>(b0);
    k_dense12<<<GN, 256>>>(b1, W2, b2, out);
}

// round 5
// speedup vs baseline: 1.1946x; 1.0177x over previous
#include <cuda_runtime.h>
#include <math.h>

#define GN   256
#define NPG  512
#define NT   (GN*NPG)
#define ET   1048576
#define SAST 130

#define DST  56
#define EPST 112
#define ACST 28

__device__ float g_Ep[(size_t)ET*EPST];
__device__ float g_D [(size_t)NT*DST];
__device__ float g_S [(size_t)NT*DST];
__device__ float g_acc[(size_t)NT*ACST];
__device__ float g_h1[(size_t)NT*26];
__device__ float g_h2[(size_t)NT*26];
__device__ float g_sm[NT];
__device__ float g_c2[GN*1920];
__device__ float g_d0[GN*512];
__device__ float g_W0T[1920*512];
__device__ float g_W1T[512*256];

__device__ __forceinline__ void fma2(unsigned long long& d, unsigned long long a,
                                     unsigned long long b) {
    asm("fma.rn.f32x2 %0, %1, %2, %0;" : "+l"(d) : "l"(a), "l"(b));
}
__device__ __forceinline__ unsigned long long bcast2(float w) {
    unsigned long long r; unsigned wi = __float_as_uint(w);
    asm("mov.b64 %0, {%1, %1};" : "=l"(r) : "r"(wi));
    return r;
}
__device__ __forceinline__ void redv4(float* p, float a, float b, float c, float d) {
    asm volatile("red.global.add.v4.f32 [%0], {%1,%2,%3,%4};"
                 :: "l"(p), "f"(a), "f"(b), "f"(c), "f"(d) : "memory");
}

// ---- Eproj GEMM: [E,52] @ Wcomb^T -> padded [E,112]
__global__ __launch_bounds__(128) void k_eproj(const float* __restrict__ ea,
        const float* __restrict__ Wf1, const float* __restrict__ Ws1,
        const float* __restrict__ Wf2, const float* __restrict__ Ws2) {
    __shared__ __align__(16) float sA[52*SAST];
    __shared__ __align__(16) float sW[52*104];
    int tid = threadIdx.x, eb = blockIdx.x * 128;
    for (int i = tid; i < 128*52; i += 128) {
        int e = i / 52, k = i - e*52;
        sA[k*SAST + e] = ea[(size_t)(eb + e)*52 + k];
    }
    for (int i = tid; i < 52*104; i += 128) {
        int k = i / 104, o = i - k*104;
        const float* W; int r;
        if      (o < 26) { W = Wf1; r = o;      }
        else if (o < 52) { W = Ws1; r = o - 26; }
        else if (o < 78) { W = Wf2; r = o - 52; }
        else             { W = Ws2; r = o - 78; }
        sW[i] = W[r*104 + 52 + k];
    }
    __syncthreads();
    int og = tid & 7, eg = tid >> 3;
    int o0 = og * 13, e0 = eg * 8;
    unsigned long long acc[4][13];
    #pragma unroll
    for (int p = 0; p < 4; p++)
        #pragma unroll
        for (int j = 0; j < 13; j++) acc[p][j] = 0ull;
    #pragma unroll 4
    for (int k = 0; k < 52; k++) {
        const unsigned long long* ap =
            reinterpret_cast<const unsigned long long*>(sA + k*SAST + e0);
        unsigned long long a0 = ap[0], a1 = ap[1], a2 = ap[2], a3 = ap[3];
        #pragma unroll
        for (int j = 0; j < 13; j++) {
            unsigned long long w2 = bcast2(sW[k*104 + o0 + j]);
            fma2(acc[0][j], a0, w2); fma2(acc[1][j], a1, w2);
            fma2(acc[2][j], a2, w2); fma2(acc[3][j], a3, w2);
        }
    }
    #pragma unroll
    for (int p = 0; p < 4; p++) {
        int e = eb + e0 + 2*p;
        #pragma unroll
        for (int j = 0; j < 13; j++) {
            int oo = o0 + j;
            int off = (oo / 26) * 28 + (oo % 26);
            float2 v = *reinterpret_cast<float2*>(&acc[p][j]);
            g_Ep[(size_t)e*EPST + off]       = v.x;
            g_Ep[(size_t)(e + 1)*EPST + off] = v.y;
        }
    }
}

// ---- node gate terms GEMM, 4-node x 13-out tiles (low reg pressure)
__global__ __launch_bounds__(256) void k_nodeproj(const float* __restrict__ xin,
        int layer, const float* __restrict__ Wf, const float* __restrict__ Ws,
        const float* __restrict__ bf, const float* __restrict__ bs) {
    __shared__ __align__(16) float sA[26*SAST];
    __shared__ __align__(16) float sW[26*104];
    __shared__ float sbias[104];
    int tid = threadIdx.x, nb = blockIdx.x * 128;
    const float* h = layer ? g_h1 : xin;
    for (int i = tid; i < 128*26; i += 256) {
        int n = i / 26, k = i - n*26;
        sA[k*SAST + n] = h[(size_t)(nb + n)*26 + k];
    }
    for (int i = tid; i < 26*104; i += 256) {
        int k = i / 104, o = i - k*104;
        int half = (o < 52) ? 0 : 26;
        int oo = (o < 52) ? o : o - 52;
        const float* W = (oo < 26) ? Wf : Ws;
        int r = (oo < 26) ? oo : oo - 26;
        sW[i] = W[r*104 + half + k];
    }
    if (tid < 104) sbias[tid] = (tid < 26) ? bf[tid] : (tid < 52 ? bs[tid-26] : 0.f);
    __syncthreads();
    int og = tid & 7, ng = tid >> 3;         // 8 out-groups x 32 node-groups
    int o0 = og * 13, n0 = ng * 4;
    unsigned long long acc[2][13];
    #pragma unroll
    for (int p = 0; p < 2; p++)
        #pragma unroll
        for (int j = 0; j < 13; j++) acc[p][j] = 0ull;
    #pragma unroll 2
    for (int k = 0; k < 26; k++) {
        const unsigned long long* ap =
            reinterpret_cast<const unsigned long long*>(sA + k*SAST + n0);
        unsigned long long a0 = ap[0], a1 = ap[1];
        #pragma unroll
        for (int j = 0; j < 13; j++) {
            unsigned long long w2 = bcast2(sW[k*104 + o0 + j]);
            fma2(acc[0][j], a0, w2); fma2(acc[1][j], a1, w2);
        }
    }
    #pragma unroll
    for (int p = 0; p < 2; p++) {
        int n = nb + n0 + 2*p;
        #pragma unroll
        for (int j = 0; j < 13; j++) {
            int oo = o0 + j;
            float bv = sbias[oo];
            int src = (oo >= 52);
            int ol = src ? oo - 52 : oo;
            int off = (ol / 26) * 28 + (ol % 26);
            float* B = src ? g_S : g_D;
            float2 v = *reinterpret_cast<float2*>(&acc[p][j]);
            B[(size_t)n*DST + off]       = v.x + bv;
            B[(size_t)(n + 1)*DST + off] = v.y + bv;
        }
    }
    if (tid < 128) {
        float4 z = make_float4(0.f, 0.f, 0.f, 0.f);
        float4* zp = reinterpret_cast<float4*>(g_acc + (size_t)(nb + tid)*ACST);
        #pragma unroll
        for (int q = 0; q < 7; q++) zp[q] = z;
    }
}

// ---- one v4 chunk of the gate/message/scatter
__device__ __forceinline__ void edge_chunk(const float* Dp, const float* Sp,
        const float* Eb, float* ap, int o) {
    float4 df = *reinterpret_cast<const float4*>(Dp + o);
    float4 ds = *reinterpret_cast<const float4*>(Dp + 28 + o);
    float4 sf = *reinterpret_cast<const float4*>(Sp + o);
    float4 ss = *reinterpret_cast<const float4*>(Sp + 28 + o);
    float4 ef = __ldcs(reinterpret_cast<const float4*>(Eb + o));
    float4 es = __ldcs(reinterpret_cast<const float4*>(Eb + 28 + o));
    float f0 = df.x+sf.x+ef.x, f1 = df.y+sf.y+ef.y;
    float f2 = df.z+sf.z+ef.z, f3 = df.w+sf.w+ef.w;
    float g0 = ds.x+ss.x+es.x, g1 = ds.y+ss.y+es.y;
    float g2 = ds.z+ss.z+es.z, g3 = ds.w+ss.w+es.w;
    float m0 = (1.f/(1.f+__expf(-f0))) * ((g0>20.f)?g0:__logf(1.f+__expf(g0)));
    float m1 = (1.f/(1.f+__expf(-f1))) * ((g1>20.f)?g1:__logf(1.f+__expf(g1)));
    float m2 = (1.f/(1.f+__expf(-f2))) * ((g2>20.f)?g2:__logf(1.f+__expf(g2)));
    float m3 = (1.f/(1.f+__expf(-f3))) * ((g3>20.f)?g3:__logf(1.f+__expf(g3)));
    redv4(ap + o, m0, m1, m2, m3);
}

// ---- per-edge gate + message + scatter; 2 threads per edge
__global__ __launch_bounds__(512) void k_edge(const int* __restrict__ ei, int layerOff) {
    int t = blockIdx.x*512 + threadIdx.x;
    int e = t >> 1, half = t & 1;
    int s = ei[e], d = ei[ET + e];
    const float* Dp = g_D + (size_t)d*DST;
    const float* Sp = g_S + (size_t)s*DST;
    const float* Eb = g_Ep + (size_t)e*EPST + layerOff;
    float* ap = g_acc + (size_t)d*ACST;
    if (half == 0) {
        edge_chunk(Dp, Sp, Eb, ap, 0);
        edge_chunk(Dp, Sp, Eb, ap, 4);
        edge_chunk(Dp, Sp, Eb, ap, 8);
        edge_chunk(Dp, Sp, Eb, ap, 12);
    } else {
        edge_chunk(Dp, Sp, Eb, ap, 16);
        edge_chunk(Dp, Sp, Eb, ap, 20);
        edge_chunk(Dp, Sp, Eb, ap, 24);   // cols 26,27 are zero-padded, unread
    }
}

__global__ void k_finalize(const float* __restrict__ xin, int layer) {
    int n = blockIdx.x*256 + threadIdx.x;
    const float* prev = layer ? g_h1 : xin;
    float* outp = layer ? g_h2 : g_h1;
    const float* ac = g_acc + (size_t)n*ACST;
    #pragma unroll
    for (int j = 0; j < 26; j++)
        outp[(size_t)n*26 + j] = tanhf(prev[(size_t)n*26 + j] + ac[j]);
}

__global__ __launch_bounds__(256) void k_softmax(const float* __restrict__ ic) {
    __shared__ float red[256];
    int g = blockIdx.x, t = threadIdx.x;
    size_t base = (size_t)g * NPG;
    float v0 = ic[base + t], v1 = ic[base + 256 + t];
    red[t] = fmaxf(v0, v1); __syncthreads();
    for (int st = 128; st > 0; st >>= 1) {
        if (t < st) red[t] = fmaxf(red[t], red[t + st]);
        __syncthreads();
    }
    float m = red[0]; __syncthreads();
    float e0 = __expf(v0 - m), e1 = __expf(v1 - m);
    red[t] = e0 + e1; __syncthreads();
    for (int st = 128; st > 0; st >>= 1) {
        if (t < st) red[t] += red[t + st];
        __syncthreads();
    }
    float inv = 1.f / red[0];
    g_sm[base + t] = e0 * inv;
    g_sm[base + 256 + t] = e1 * inv;
}

__global__ __launch_bounds__(256) void k_sortpool(const float* __restrict__ Wc1,
        const float* __restrict__ bc1, const float* __restrict__ Wc2,
        const float* __restrict__ bc2) {
    __shared__ float sv[512];
    __shared__ unsigned short si[512];
    __shared__ float pf[128*53];
    __shared__ float m16[16*64];
    __shared__ float swc1[16*53];
    __shared__ float swc2[2560];
    __shared__ float sb1[16], sb2[32];
    int g = blockIdx.x, t = threadIdx.x;
    size_t nb = (size_t)g * NPG;
    sv[t] = g_sm[nb + t];           si[t] = (unsigned short)t;
    sv[t+256] = g_sm[nb + 256 + t]; si[t+256] = (unsigned short)(t + 256);
    for (int i = t; i < 16*53; i += 256) swc1[i] = Wc1[i];
    for (int i = t; i < 2560;  i += 256) swc2[i] = Wc2[i];
    if (t < 16) sb1[t] = bc1[t];
    if (t < 32) sb2[t] = bc2[t];
    __syncthreads();
    for (int size = 2; size <= 512; size <<= 1) {
        for (int stride = size >> 1; stride > 0; stride >>= 1) {
            int q = t / stride, r = t - q*stride;
            int i = q*2*stride + r, j = i + stride;
            bool dir = ((i & size) == 0);
            float av = sv[i], bv = sv[j];
            int ai = si[i], bi = si[j];
            bool before = (av > bv) || (av == bv && ai < bi);
            if (dir ? !before : before) {
                sv[i] = bv; sv[j] = av;
                si[i] = (unsigned short)bi; si[j] = (unsigned short)ai;
            }
            __syncthreads();
        }
    }
    for (int i = t; i < 128*53; i += 256) {
        int k = i / 53, l = i - k*53;
        int node = (int)nb + (int)si[k];
        float v;
        if (l < 26)      v = g_h1[(size_t)node*26 + l];
        else if (l < 52) v = g_h2[(size_t)node*26 + l - 26];
        else             v = sv[k];
        pf[i] = v;
    }
    __syncthreads();
    for (int task = t; task < 1024; task += 256) {
        int c = task & 15, j = task >> 4;
        const float* w  = swc1 + c*53;
        const float* p0 = pf + (2*j)*53;
        const float* p1 = p0 + 53;
        float a = sb1[c], b = sb1[c];
        #pragma unroll 13
        for (int l = 0; l < 53; l++) { a += w[l]*p0[l]; b += w[l]*p1[l]; }
        a = fmaxf(a, 0.f); b = fmaxf(b, 0.f);
        m16[c*64 + j] = fmaxf(a, b);
    }
    __syncthreads();
    for (int task = t; task < 1920; task += 256) {
        int oc = task / 60, p = task - oc*60;
        float acc = sb2[oc];
        #pragma unroll 4
        for (int ic2 = 0; ic2 < 16; ic2++) {
            const float* w  = swc2 + (oc*16 + ic2)*5;
            const float* mm = m16 + ic2*64 + p;
            #pragma unroll
            for (int u = 0; u < 5; u++) acc += w[u]*mm[u];
        }
        g_c2[g*1920 + task] = fmaxf(acc, 0.f);
    }
}

__global__ void k_transW0(const float* __restrict__ W0) {
    int i = blockIdx.x*256 + threadIdx.x;
    int k = i >> 9, o = i & 511;
    g_W0T[i] = W0[o*1920 + k];
}
__global__ void k_transW1(const float* __restrict__ W1) {
    int i = blockIdx.x*256 + threadIdx.x;
    int k = i >> 8, o = i & 255;
    g_W1T[i] = W1[o*512 + k];
}

__global__ __launch_bounds__(256) void k_dense0(const float* __restrict__ b0) {
    __shared__ float sA[4*1920];
    int t = threadIdx.x, gb = blockIdx.x*4;
    for (int i = t; i < 4*1920; i += 256) sA[i] = g_c2[gb*1920 + i];
    __syncthreads();
    float bb0 = b0[t], bb1 = b0[t + 256];
    float acc0[4], acc1[4];
    #pragma unroll
    for (int g2 = 0; g2 < 4; g2++) { acc0[g2] = bb0; acc1[g2] = bb1; }
    for (int k = 0; k < 1920; k++) {
        float w0 = g_W0T[k*512 + t];
        float w1 = g_W0T[k*512 + t + 256];
        #pragma unroll
        for (int g2 = 0; g2 < 4; g2++) {
            float a = sA[g2*1920 + k];
            acc0[g2] += a*w0; acc1[g2] += a*w1;
        }
    }
    #pragma unroll
    for (int g2 = 0; g2 < 4; g2++) {
        g_d0[(gb + g2)*512 + t]       = fmaxf(acc0[g2], 0.f);
        g_d0[(gb + g2)*512 + t + 256] = fmaxf(acc1[g2], 0.f);
    }
}

__global__ __launch_bounds__(256) void k_dense12(const float* __restrict__ b1,
        const float* __restrict__ W2, const float* __restrict__ b2,
        float* __restrict__ out) {
    __shared__ float sd[512];
    __shared__ float red[256];
    int g = blockIdx.x, t = threadIdx.x;
    sd[t] = g_d0[g*512 + t]; sd[t+256] = g_d0[g*512 + 256 + t];
    __syncthreads();
    float acc = b1[t];
    #pragma unroll 8
    for (int k = 0; k < 512; k++) acc += sd[k] * g_W1T[k*256 + t];
    red[t] = fmaxf(acc, 0.f) * W2[t];
    __syncthreads();
    for (int st = 128; st > 0; st >>= 1) {
        if (t < st) red[t] += red[t + st];
        __syncthreads();
    }
    if (t == 0) out[g] = red[0] + b2[0];
}

extern "C" void kernel_launch(void* const* d_in, const int* in_sizes, int n_in,
                              void* d_out, int out_size) {
    const float* x   = (const float*)d_in[0];
    const float* ea  = (const float*)d_in[1];
    const float* ic  = (const float*)d_in[2];
    const float* Wf1 = (const float*)d_in[3];
    const float* bf1 = (const float*)d_in[4];
    const float* Ws1 = (const float*)d_in[5];
    const float* bs1 = (const float*)d_in[6];
    const float* Wf2 = (const float*)d_in[7];
    const float* bf2 = (const float*)d_in[8];
    const float* Ws2 = (const float*)d_in[9];
    const float* bs2 = (const float*)d_in[10];
    const float* Wc1 = (const float*)d_in[11];
    const float* bc1 = (const float*)d_in[12];
    const float* Wc2 = (const float*)d_in[13];
    const float* bc2 = (const float*)d_in[14];
    const float* W0  = (const float*)d_in[15];
    const float* b0  = (const float*)d_in[16];
    const float* W1  = (const float*)d_in[17];
    const float* b1  = (const float*)d_in[18];
    const float* W2  = (const float*)d_in[19];
    const float* b2  = (const float*)d_in[20];
    const int*   ei  = (const int*)d_in[21];
    float* out = (float*)d_out;

    // order chosen so k_edge lands on the ncu-profiled launch slot
    k_eproj<<<ET/128, 128>>>(ea, Wf1, Ws1, Wf2, Ws2);
    k_nodeproj<<<NT/128, 256>>>(x, 0, Wf1, Ws1, bf1, bs1);
    k_transW0<<<3840, 256>>>(W0);
    k_edge<<<ET/256, 512>>>(ei, 0);
    k_finalize<<<NT/256, 256>>>(x, 0);

    k_nodeproj<<<NT/128, 256>>>(x, 1, Wf2, Ws2, bf2, bs2);
    k_edge<<<ET/256, 512>>>(ei, 56);
    k_finalize<<<NT/256, 256>>>(x, 1);

    k_transW1<<<512, 256>>>(W1);
    k_softmax<<<GN, 256>>>(ic);
    k_sortpool<<<GN, 256>>>(Wc1, bc1, Wc2, bc2);
    k_dense0<<<GN/4, 256>>>(b0);
    k_dense12<<<GN, 256>>>(b1, W2, b2, out);
}

// round 6
// speedup vs baseline: 1.3856x; 1.1598x over previous
#include <cuda_runtime.h>
#include <math.h>

#define GN   256
#define NPG  512
#define NT   (GN*NPG)
#define ET   1048576
#define SAST 130

#define DSST 112     // g_DS row: [D-f 0..25|pad|D-s 28..53|pad|S-f 56..81|pad|S-s 84..109|pad]
#define EPST 112     // g_Ep row: [L1f|pad|L1s|pad|L2f|pad|L2s|pad]
#define ACST 28

__device__ float g_Ep[(size_t)ET*EPST];
__device__ float g_DS[(size_t)NT*DSST];
__device__ float g_acc[(size_t)NT*ACST];
__device__ float g_h1[(size_t)NT*26];
__device__ float g_h2[(size_t)NT*26];
__device__ float g_sm[NT];
__device__ float g_c2[GN*1920];
__device__ float g_d0[GN*512];
__device__ float g_W0T[1920*512];
__device__ float g_W1T[512*256];

__device__ __forceinline__ void fma2(unsigned long long& d, unsigned long long a,
                                     unsigned long long b) {
    asm("fma.rn.f32x2 %0, %1, %2, %0;" : "+l"(d) : "l"(a), "l"(b));
}
__device__ __forceinline__ unsigned long long bcast2(float w) {
    unsigned long long r; unsigned wi = __float_as_uint(w);
    asm("mov.b64 %0, {%1, %1};" : "=l"(r) : "r"(wi));
    return r;
}
__device__ __forceinline__ void redv4(float* p, float a, float b, float c, float d) {
    asm volatile("red.global.add.v4.f32 [%0], {%1,%2,%3,%4};"
                 :: "l"(p), "f"(a), "f"(b), "f"(c), "f"(d) : "memory");
}

// ---- Eproj GEMM: [E,52] @ Wcomb^T -> padded [E,112], staged coalesced stores
__global__ __launch_bounds__(128) void k_eproj(const float* __restrict__ ea,
        const float* __restrict__ Wf1, const float* __restrict__ Ws1,
        const float* __restrict__ Wf2, const float* __restrict__ Ws2) {
    __shared__ __align__(16) char s_raw[48672];
    float* sA = (float*)s_raw;                    // 52*130 floats
    float* sW = (float*)(s_raw + 27040);          // 52*104 floats
    float* stage = (float*)s_raw;                 // reused after FMA: 32*112
    int tid = threadIdx.x, eb = blockIdx.x * 128;
    for (int i = tid; i < 128*52; i += 128) {
        int e = i / 52, k = i - e*52;
        sA[k*SAST + e] = ea[(size_t)(eb + e)*52 + k];
    }
    for (int i = tid; i < 52*104; i += 128) {
        int k = i / 104, o = i - k*104;
        const float* W; int r;
        if      (o < 26) { W = Wf1; r = o;      }
        else if (o < 52) { W = Ws1; r = o - 26; }
        else if (o < 78) { W = Wf2; r = o - 52; }
        else             { W = Ws2; r = o - 78; }
        sW[i] = W[r*104 + 52 + k];
    }
    __syncthreads();
    int og = tid & 7, eg = tid >> 3;
    int o0 = og * 13, e0 = eg * 8;
    unsigned long long acc[4][13];
    #pragma unroll
    for (int p = 0; p < 4; p++)
        #pragma unroll
        for (int j = 0; j < 13; j++) acc[p][j] = 0ull;
    #pragma unroll 4
    for (int k = 0; k < 52; k++) {
        const unsigned long long* ap =
            reinterpret_cast<const unsigned long long*>(sA + k*SAST + e0);
        unsigned long long a0 = ap[0], a1 = ap[1], a2 = ap[2], a3 = ap[3];
        #pragma unroll
        for (int j = 0; j < 13; j++) {
            unsigned long long w2 = bcast2(sW[k*104 + o0 + j]);
            fma2(acc[0][j], a0, w2); fma2(acc[1][j], a1, w2);
            fma2(acc[2][j], a2, w2); fma2(acc[3][j], a3, w2);
        }
    }
    // staged, coalesced output: 4 passes of 32 edges
    for (int pass = 0; pass < 4; pass++) {
        __syncthreads();
        if (eg >= pass*4 && eg < pass*4 + 4) {
            int rbase = e0 - pass*32;
            #pragma unroll
            for (int p = 0; p < 4; p++) {
                #pragma unroll
                for (int j = 0; j < 13; j++) {
                    int oo = o0 + j;
                    int off = (oo / 26) * 28 + (oo % 26);
                    float2 v = *reinterpret_cast<float2*>(&acc[p][j]);
                    stage[(rbase + 2*p)*112 + off]     = v.x;
                    stage[(rbase + 2*p + 1)*112 + off] = v.y;
                }
            }
        }
        __syncthreads();
        float4* dst = reinterpret_cast<float4*>(g_Ep + ((size_t)eb + pass*32)*EPST);
        const float4* srcp = reinterpret_cast<const float4*>(stage);
        for (int i = tid; i < 896; i += 128) dst[i] = srcp[i];
    }
}

// ---- node gate terms GEMM -> g_DS, staged coalesced stores; zero acc
__global__ __launch_bounds__(256) void k_nodeproj(const float* __restrict__ xin,
        int layer, const float* __restrict__ Wf, const float* __restrict__ Ws,
        const float* __restrict__ bf, const float* __restrict__ bs) {
    __shared__ __align__(16) char s_raw[39104];
    float* sA    = (float*)s_raw;                 // 26*130
    float* sW    = (float*)(s_raw + 13520);       // 26*104
    float* sbias = (float*)(s_raw + 24336);       // 104
    float* stage = (float*)(s_raw + 24752);       // 32*112
    int tid = threadIdx.x, nb = blockIdx.x * 128;
    const float* h = layer ? g_h1 : xin;
    for (int i = tid; i < 128*26; i += 256) {
        int n = i / 26, k = i - n*26;
        sA[k*SAST + n] = h[(size_t)(nb + n)*26 + k];
    }
    for (int i = tid; i < 26*104; i += 256) {
        int k = i / 104, o = i - k*104;
        int half = (o < 52) ? 0 : 26;
        int oo = (o < 52) ? o : o - 52;
        const float* W = (oo < 26) ? Wf : Ws;
        int r = (oo < 26) ? oo : oo - 26;
        sW[i] = W[r*104 + half + k];
    }
    if (tid < 104) sbias[tid] = (tid < 26) ? bf[tid] : (tid < 52 ? bs[tid-26] : 0.f);
    __syncthreads();
    int og = tid & 7, ng = tid >> 3;              // 8 out-groups x 32 node-groups
    int o0 = og * 13, n0 = ng * 4;
    unsigned long long acc[2][13];
    #pragma unroll
    for (int p = 0; p < 2; p++)
        #pragma unroll
        for (int j = 0; j < 13; j++) acc[p][j] = 0ull;
    #pragma unroll 2
    for (int k = 0; k < 26; k++) {
        const unsigned long long* ap =
            reinterpret_cast<const unsigned long long*>(sA + k*SAST + n0);
        unsigned long long a0 = ap[0], a1 = ap[1];
        #pragma unroll
        for (int j = 0; j < 13; j++) {
            unsigned long long w2 = bcast2(sW[k*104 + o0 + j]);
            fma2(acc[0][j], a0, w2); fma2(acc[1][j], a1, w2);
        }
    }
    for (int pass = 0; pass < 4; pass++) {
        __syncthreads();
        if (ng >= pass*8 && ng < pass*8 + 8) {
            int rbase = n0 - pass*32;
            #pragma unroll
            for (int p = 0; p < 2; p++) {
                #pragma unroll
                for (int j = 0; j < 13; j++) {
                    int oo = o0 + j;
                    float bv = sbias[oo];
                    int src = (oo >= 52);
                    int ol = src ? oo - 52 : oo;
                    int off = (src ? 56 : 0) + (ol / 26) * 28 + (ol % 26);
                    float2 v = *reinterpret_cast<float2*>(&acc[p][j]);
                    stage[(rbase + 2*p)*112 + off]     = v.x + bv;
                    stage[(rbase + 2*p + 1)*112 + off] = v.y + bv;
                }
            }
        }
        __syncthreads();
        float4* dst = reinterpret_cast<float4*>(g_DS + ((size_t)nb + pass*32)*DSST);
        const float4* srcp = reinterpret_cast<const float4*>(stage);
        for (int i = tid; i < 896; i += 256) dst[i] = srcp[i];
    }
    if (tid < 128) {
        float4 z = make_float4(0.f, 0.f, 0.f, 0.f);
        float4* zp = reinterpret_cast<float4*>(g_acc + (size_t)(nb + tid)*ACST);
        #pragma unroll
        for (int q = 0; q < 7; q++) zp[q] = z;
    }
}

// ---- one v4 chunk of gate/message/scatter
__device__ __forceinline__ void edge_chunk(const float* Dp, const float* Sp,
        const float* Eb, float* ap, int o) {
    float4 df = *reinterpret_cast<const float4*>(Dp + o);
    float4 ds = *reinterpret_cast<const float4*>(Dp + 28 + o);
    float4 sf = *reinterpret_cast<const float4*>(Sp + o);
    float4 ss = *reinterpret_cast<const float4*>(Sp + 28 + o);
    float4 ef = __ldcs(reinterpret_cast<const float4*>(Eb + o));
    float4 es = __ldcs(reinterpret_cast<const float4*>(Eb + 28 + o));
    float f0 = df.x+sf.x+ef.x, f1 = df.y+sf.y+ef.y;
    float f2 = df.z+sf.z+ef.z, f3 = df.w+sf.w+ef.w;
    float g0 = ds.x+ss.x+es.x, g1 = ds.y+ss.y+es.y;
    float g2 = ds.z+ss.z+es.z, g3 = ds.w+ss.w+es.w;
    float m0 = (1.f/(1.f+__expf(-f0))) * ((g0>20.f)?g0:__logf(1.f+__expf(g0)));
    float m1 = (1.f/(1.f+__expf(-f1))) * ((g1>20.f)?g1:__logf(1.f+__expf(g1)));
    float m2 = (1.f/(1.f+__expf(-f2))) * ((g2>20.f)?g2:__logf(1.f+__expf(g2)));
    float m3 = (1.f/(1.f+__expf(-f3))) * ((g3>20.f)?g3:__logf(1.f+__expf(g3)));
    redv4(ap + o, m0, m1, m2, m3);
}

// ---- per-edge gate + message + scatter; 2 threads per edge
__global__ __launch_bounds__(512) void k_edge(const int* __restrict__ ei, int layerOff) {
    int t = blockIdx.x*512 + threadIdx.x;
    int e = t >> 1, half = t & 1;
    int s = ei[e], d = ei[ET + e];
    const float* Dp = g_DS + (size_t)d*DSST;
    const float* Sp = g_DS + (size_t)s*DSST + 56;
    const float* Eb = g_Ep + (size_t)e*EPST + layerOff;
    float* ap = g_acc + (size_t)d*ACST;
    if (half == 0) {
        edge_chunk(Dp, Sp, Eb, ap, 0);
        edge_chunk(Dp, Sp, Eb, ap, 4);
        edge_chunk(Dp, Sp, Eb, ap, 8);
        edge_chunk(Dp, Sp, Eb, ap, 12);
    } else {
        edge_chunk(Dp, Sp, Eb, ap, 16);
        edge_chunk(Dp, Sp, Eb, ap, 20);
        edge_chunk(Dp, Sp, Eb, ap, 24);   // pad lanes land in unread acc pads
    }
}

__global__ void k_finalize(const float* __restrict__ xin, int layer) {
    int n = blockIdx.x*256 + threadIdx.x;
    const float* prev = layer ? g_h1 : xin;
    float* outp = layer ? g_h2 : g_h1;
    const float* ac = g_acc + (size_t)n*ACST;
    #pragma unroll
    for (int j = 0; j < 26; j++)
        outp[(size_t)n*26 + j] = tanhf(prev[(size_t)n*26 + j] + ac[j]);
}

__global__ __launch_bounds__(256) void k_softmax(const float* __restrict__ ic) {
    __shared__ float red[256];
    int g = blockIdx.x, t = threadIdx.x;
    size_t base = (size_t)g * NPG;
    float v0 = ic[base + t], v1 = ic[base + 256 + t];
    red[t] = fmaxf(v0, v1); __syncthreads();
    for (int st = 128; st > 0; st >>= 1) {
        if (t < st) red[t] = fmaxf(red[t], red[t + st]);
        __syncthreads();
    }
    float m = red[0]; __syncthreads();
    float e0 = __expf(v0 - m), e1 = __expf(v1 - m);
    red[t] = e0 + e1; __syncthreads();
    for (int st = 128; st > 0; st >>= 1) {
        if (t < st) red[t] += red[t + st];
        __syncthreads();
    }
    float inv = 1.f / red[0];
    g_sm[base + t] = e0 * inv;
    g_sm[base + 256 + t] = e1 * inv;
}

__global__ __launch_bounds__(256) void k_sortpool(const float* __restrict__ Wc1,
        const float* __restrict__ bc1, const float* __restrict__ Wc2,
        const float* __restrict__ bc2) {
    __shared__ float sv[512];
    __shared__ unsigned short si[512];
    __shared__ float pf[128*53];
    __shared__ float m16[16*64];
    __shared__ float swc1[16*53];
    __shared__ float swc2[2560];
    __shared__ float sb1[16], sb2[32];
    int g = blockIdx.x, t = threadIdx.x;
    size_t nb = (size_t)g * NPG;
    sv[t] = g_sm[nb + t];           si[t] = (unsigned short)t;
    sv[t+256] = g_sm[nb + 256 + t]; si[t+256] = (unsigned short)(t + 256);
    for (int i = t; i < 16*53; i += 256) swc1[i] = Wc1[i];
    for (int i = t; i < 2560;  i += 256) swc2[i] = Wc2[i];
    if (t < 16) sb1[t] = bc1[t];
    if (t < 32) sb2[t] = bc2[t];
    __syncthreads();
    for (int size = 2; size <= 512; size <<= 1) {
        for (int stride = size >> 1; stride > 0; stride >>= 1) {
            int q = t / stride, r = t - q*stride;
            int i = q*2*stride + r, j = i + stride;
            bool dir = ((i & size) == 0);
            float av = sv[i], bv = sv[j];
            int ai = si[i], bi = si[j];
            bool before = (av > bv) || (av == bv && ai < bi);
            if (dir ? !before : before) {
                sv[i] = bv; sv[j] = av;
                si[i] = (unsigned short)bi; si[j] = (unsigned short)ai;
            }
            __syncthreads();
        }
    }
    for (int i = t; i < 128*53; i += 256) {
        int k = i / 53, l = i - k*53;
        int node = (int)nb + (int)si[k];
        float v;
        if (l < 26)      v = g_h1[(size_t)node*26 + l];
        else if (l < 52) v = g_h2[(size_t)node*26 + l - 26];
        else             v = sv[k];
        pf[i] = v;
    }
    __syncthreads();
    for (int task = t; task < 1024; task += 256) {
        int c = task & 15, j = task >> 4;
        const float* w  = swc1 + c*53;
        const float* p0 = pf + (2*j)*53;
        const float* p1 = p0 + 53;
        float a = sb1[c], b = sb1[c];
        #pragma unroll 13
        for (int l = 0; l < 53; l++) { a += w[l]*p0[l]; b += w[l]*p1[l]; }
        a = fmaxf(a, 0.f); b = fmaxf(b, 0.f);
        m16[c*64 + j] = fmaxf(a, b);
    }
    __syncthreads();
    for (int task = t; task < 1920; task += 256) {
        int oc = task / 60, p = task - oc*60;
        float acc = sb2[oc];
        #pragma unroll 4
        for (int ic2 = 0; ic2 < 16; ic2++) {
            const float* w  = swc2 + (oc*16 + ic2)*5;
            const float* mm = m16 + ic2*64 + p;
            #pragma unroll
            for (int u = 0; u < 5; u++) acc += w[u]*mm[u];
        }
        g_c2[g*1920 + task] = fmaxf(acc, 0.f);
    }
}

__global__ void k_transW0(const float* __restrict__ W0) {
    int i = blockIdx.x*256 + threadIdx.x;
    int k = i >> 9, o = i & 511;
    g_W0T[i] = W0[o*1920 + k];
}
__global__ void k_transW1(const float* __restrict__ W1) {
    int i = blockIdx.x*256 + threadIdx.x;
    int k = i >> 8, o = i & 255;
    g_W1T[i] = W1[o*512 + k];
}

__global__ __launch_bounds__(256) void k_dense0(const float* __restrict__ b0) {
    __shared__ float sA[4*1920];
    int t = threadIdx.x, gb = blockIdx.x*4;
    for (int i = t; i < 4*1920; i += 256) sA[i] = g_c2[gb*1920 + i];
    __syncthreads();
    float bb0 = b0[t], bb1 = b0[t + 256];
    float acc0[4], acc1[4];
    #pragma unroll
    for (int g2 = 0; g2 < 4; g2++) { acc0[g2] = bb0; acc1[g2] = bb1; }
    for (int k = 0; k < 1920; k++) {
        float w0 = g_W0T[k*512 + t];
        float w1 = g_W0T[k*512 + t + 256];
        #pragma unroll
        for (int g2 = 0; g2 < 4; g2++) {
            float a = sA[g2*1920 + k];
            acc0[g2] += a*w0; acc1[g2] += a*w1;
        }
    }
    #pragma unroll
    for (int g2 = 0; g2 < 4; g2++) {
        g_d0[(gb + g2)*512 + t]       = fmaxf(acc0[g2], 0.f);
        g_d0[(gb + g2)*512 + t + 256] = fmaxf(acc1[g2], 0.f);
    }
}

__global__ __launch_bounds__(256) void k_dense12(const float* __restrict__ b1,
        const float* __restrict__ W2, const float* __restrict__ b2,
        float* __restrict__ out) {
    __shared__ float sd[512];
    __shared__ float red[256];
    int g = blockIdx.x, t = threadIdx.x;
    sd[t] = g_d0[g*512 + t]; sd[t+256] = g_d0[g*512 + 256 + t];
    __syncthreads();
    float acc = b1[t];
    #pragma unroll 8
    for (int k = 0; k < 512; k++) acc += sd[k] * g_W1T[k*256 + t];
    red[t] = fmaxf(acc, 0.f) * W2[t];
    __syncthreads();
    for (int st = 128; st > 0; st >>= 1) {
        if (t < st) red[t] += red[t + st];
        __syncthreads();
    }
    if (t == 0) out[g] = red[0] + b2[0];
}

extern "C" void kernel_launch(void* const* d_in, const int* in_sizes, int n_in,
                              void* d_out, int out_size) {
    const float* x   = (const float*)d_in[0];
    const float* ea  = (const float*)d_in[1];
    const float* ic  = (const float*)d_in[2];
    const float* Wf1 = (const float*)d_in[3];
    const float* bf1 = (const float*)d_in[4];
    const float* Ws1 = (const float*)d_in[5];
    const float* bs1 = (const float*)d_in[6];
    const float* Wf2 = (const float*)d_in[7];
    const float* bf2 = (const float*)d_in[8];
    const float* Ws2 = (const float*)d_in[9];
    const float* bs2 = (const float*)d_in[10];
    const float* Wc1 = (const float*)d_in[11];
    const float* bc1 = (const float*)d_in[12];
    const float* Wc2 = (const float*)d_in[13];
    const float* bc2 = (const float*)d_in[14];
    const float* W0  = (const float*)d_in[15];
    const float* b0  = (const float*)d_in[16];
    const float* W1  = (const float*)d_in[17];
    const float* b1  = (const float*)d_in[18];
    const float* W2  = (const float*)d_in[19];
    const float* b2  = (const float*)d_in[20];
    const int*   ei  = (const int*)d_in[21];
    float* out = (float*)d_out;

    // k_eproj placed 4th so the ncu slot profiles it
    k_transW0<<<3840, 256>>>(W0);
    k_transW1<<<512, 256>>>(W1);
    k_softmax<<<GN, 256>>>(ic);
    k_eproj<<<ET/128, 128>>>(ea, Wf1, Ws1, Wf2, Ws2);

    k_nodeproj<<<NT/128, 256>>>(x, 0, Wf1, Ws1, bf1, bs1);
    k_edge<<<ET/256, 512>>>(ei, 0);
    k_finalize<<<NT/256, 256>>>(x, 0);

    k_nodeproj<<<NT/128, 256>>>(x, 1, Wf2, Ws2, bf2, bs2);
    k_edge<<<ET/256, 512>>>(ei, 56);
    k_finalize<<<NT/256, 256>>>(x, 1);

    k_sortpool<<<GN, 256>>>(Wc1, bc1, Wc2, bc2);
    k_dense0<<<GN/4, 256>>>(b0);
    k_dense12<<<GN, 256>>>(b1, W2, b2, out);
}

// round 7
// speedup vs baseline: 1.4822x; 1.0698x over previous
#include <cuda_runtime.h>
#include <math.h>

#define GN   256
#define NPG  512
#define NT   (GN*NPG)
#define ET   1048576
#define SAST 130

#define DSST 112     // g_DS row: [D-f|pad|D-s|pad|S-f|pad|S-s|pad] (28 apart)
#define EPST 56      // g_Ep row (L2 only): [f 0..25|pad|s 28..53|pad]
#define ACST 28

__device__ float g_Ep[(size_t)ET*EPST];
__device__ float g_DS[(size_t)NT*DSST];
__device__ float g_acc[(size_t)NT*ACST];
__device__ float g_h1[(size_t)NT*26];
__device__ float g_h2[(size_t)NT*26];
__device__ float g_sm[NT];
__device__ float g_c2[GN*1920];
__device__ float g_d0[GN*512];
__device__ float g_W0T[1920*512];
__device__ float g_W1T[512*256];

__device__ __forceinline__ void fma2(unsigned long long& d, unsigned long long a,
                                     unsigned long long b) {
    asm("fma.rn.f32x2 %0, %1, %2, %0;" : "+l"(d) : "l"(a), "l"(b));
}
__device__ __forceinline__ unsigned long long bcast2(float w) {
    unsigned long long r; unsigned wi = __float_as_uint(w);
    asm("mov.b64 %0, {%1, %1};" : "=l"(r) : "r"(wi));
    return r;
}
__device__ __forceinline__ void redv4(float* p, float a, float b, float c, float d) {
    asm volatile("red.global.add.v4.f32 [%0], {%1,%2,%3,%4};"
                 :: "l"(p), "f"(a), "f"(b), "f"(c), "f"(d) : "memory");
}

// message for 4 consecutive gate lanes
__device__ __forceinline__ void msg4(const float4 df, const float4 ds,
        const float4 sf, const float4 ss, const float4 ef, const float4 es,
        float& m0, float& m1, float& m2, float& m3) {
    float f0 = df.x+sf.x+ef.x, f1 = df.y+sf.y+ef.y;
    float f2 = df.z+sf.z+ef.z, f3 = df.w+sf.w+ef.w;
    float g0 = ds.x+ss.x+es.x, g1 = ds.y+ss.y+es.y;
    float g2 = ds.z+ss.z+es.z, g3 = ds.w+ss.w+es.w;
    m0 = (1.f/(1.f+__expf(-f0))) * ((g0>20.f)?g0:__logf(1.f+__expf(g0)));
    m1 = (1.f/(1.f+__expf(-f1))) * ((g1>20.f)?g1:__logf(1.f+__expf(g1)));
    m2 = (1.f/(1.f+__expf(-f2))) * ((g2>20.f)?g2:__logf(1.f+__expf(g2)));
    m3 = (1.f/(1.f+__expf(-f3))) * ((g3>20.f)?g3:__logf(1.f+__expf(g3)));
}

// ---- fused: Eproj GEMM (both layers) + layer-1 edge combine; store L2 Ep only
__global__ __launch_bounds__(256) void k_eproj_fused(const float* __restrict__ ea,
        const float* __restrict__ Wf1, const float* __restrict__ Ws1,
        const float* __restrict__ Wf2, const float* __restrict__ Ws2,
        const int* __restrict__ ei) {
    __shared__ __align__(16) char s_raw[48928];
    float* sA    = (float*)s_raw;                 // 52*130 f (reused as stage 32*112)
    float* sW    = (float*)(s_raw + 27040);       // 52*104 f
    int*   sedge = (int*)(s_raw + 48672);         // 32*2
    float* stage = (float*)s_raw;
    int tid = threadIdx.x, eb = blockIdx.x * 128;
    for (int i = tid; i < 128*52; i += 256) {
        int e = i / 52, k = i - e*52;
        sA[k*SAST + e] = ea[(size_t)(eb + e)*52 + k];
    }
    for (int i = tid; i < 52*104; i += 256) {
        int k = i / 104, o = i - k*104;
        const float* W; int r;
        if      (o < 26) { W = Wf1; r = o;      }
        else if (o < 52) { W = Ws1; r = o - 26; }
        else if (o < 78) { W = Wf2; r = o - 52; }
        else             { W = Ws2; r = o - 78; }
        sW[i] = W[r*104 + 52 + k];
    }
    __syncthreads();
    int og = tid & 7, eg = tid >> 3;              // 8 out-groups x 32 edge-groups
    int o0 = og * 13, e0 = eg * 4;
    unsigned long long acc[2][13];
    #pragma unroll
    for (int p = 0; p < 2; p++)
        #pragma unroll
        for (int j = 0; j < 13; j++) acc[p][j] = 0ull;
    #pragma unroll 4
    for (int k = 0; k < 52; k++) {
        const unsigned long long* ap =
            reinterpret_cast<const unsigned long long*>(sA + k*SAST + e0);
        unsigned long long a0 = ap[0], a1 = ap[1];
        #pragma unroll
        for (int j = 0; j < 13; j++) {
            unsigned long long w2 = bcast2(sW[k*104 + o0 + j]);
            fma2(acc[0][j], a0, w2); fma2(acc[1][j], a1, w2);
        }
    }
    // 4 passes x 32 edges: stage -> (flush L2 part) + (L1 combine/scatter)
    for (int pass = 0; pass < 4; pass++) {
        __syncthreads();
        if (eg >= pass*8 && eg < pass*8 + 8) {
            int rbase = e0 - pass*32;
            #pragma unroll
            for (int p = 0; p < 2; p++) {
                #pragma unroll
                for (int j = 0; j < 13; j++) {
                    int oo = o0 + j;
                    int off = (oo / 26) * 28 + (oo % 26);   // 0..111 padded
                    float2 v = *reinterpret_cast<float2*>(&acc[p][j]);
                    stage[(rbase + 2*p)*112 + off]     = v.x;
                    stage[(rbase + 2*p + 1)*112 + off] = v.y;
                }
            }
        }
        if (tid < 32) {
            sedge[tid*2]     = ei[eb + pass*32 + tid];        // src
            sedge[tid*2 + 1] = ei[ET + eb + pass*32 + tid];   // dst
        }
        __syncthreads();
        // flush L2 half (stage cols 56..111 -> g_Ep rows of 56), coalesced
        {
            float4* dst = reinterpret_cast<float4*>(g_Ep + ((size_t)eb + pass*32)*EPST);
            for (int i = tid; i < 448; i += 256) {
                int e = i / 14, q = i - e*14;
                dst[i] = *reinterpret_cast<const float4*>(stage + e*112 + 56 + q*4);
            }
        }
        // layer-1 combine: 32 edges x 7 chunks
        if (tid < 224) {
            int el = tid / 7, c = tid - el*7, o = c*4;
            int s = sedge[el*2], d = sedge[el*2 + 1];
            const float* Dp = g_DS + (size_t)d*DSST;
            const float* Sp = g_DS + (size_t)s*DSST + 56;
            const float* Eb = stage + el*112;
            float4 df = *reinterpret_cast<const float4*>(Dp + o);
            float4 ds = *reinterpret_cast<const float4*>(Dp + 28 + o);
            float4 sf = *reinterpret_cast<const float4*>(Sp + o);
            float4 ss = *reinterpret_cast<const float4*>(Sp + 28 + o);
            float4 ef = *reinterpret_cast<const float4*>(Eb + o);
            float4 es = *reinterpret_cast<const float4*>(Eb + 28 + o);
            float m0, m1, m2, m3;
            msg4(df, ds, sf, ss, ef, es, m0, m1, m2, m3);
            redv4(g_acc + (size_t)d*ACST + o, m0, m1, m2, m3);
        }
    }
}

// ---- node gate terms GEMM -> g_DS, staged coalesced stores; zero acc
__global__ __launch_bounds__(256) void k_nodeproj(const float* __restrict__ xin,
        int layer, const float* __restrict__ Wf, const float* __restrict__ Ws,
        const float* __restrict__ bf, const float* __restrict__ bs) {
    __shared__ __align__(16) char s_raw[39104];
    float* sA    = (float*)s_raw;                 // 26*130
    float* sW    = (float*)(s_raw + 13520);       // 26*104
    float* sbias = (float*)(s_raw + 24336);       // 104
    float* stage = (float*)(s_raw + 24752);       // 32*112
    int tid = threadIdx.x, nb = blockIdx.x * 128;
    const float* h = layer ? g_h1 : xin;
    for (int i = tid; i < 128*26; i += 256) {
        int n = i / 26, k = i - n*26;
        sA[k*SAST + n] = h[(size_t)(nb + n)*26 + k];
    }
    for (int i = tid; i < 26*104; i += 256) {
        int k = i / 104, o = i - k*104;
        int half = (o < 52) ? 0 : 26;
        int oo = (o < 52) ? o : o - 52;
        const float* W = (oo < 26) ? Wf : Ws;
        int r = (oo < 26) ? oo : oo - 26;
        sW[i] = W[r*104 + half + k];
    }
    if (tid < 104) sbias[tid] = (tid < 26) ? bf[tid] : (tid < 52 ? bs[tid-26] : 0.f);
    __syncthreads();
    int og = tid & 7, ng = tid >> 3;
    int o0 = og * 13, n0 = ng * 4;
    unsigned long long acc[2][13];
    #pragma unroll
    for (int p = 0; p < 2; p++)
        #pragma unroll
        for (int j = 0; j < 13; j++) acc[p][j] = 0ull;
    #pragma unroll 2
    for (int k = 0; k < 26; k++) {
        const unsigned long long* ap =
            reinterpret_cast<const unsigned long long*>(sA + k*SAST + n0);
        unsigned long long a0 = ap[0], a1 = ap[1];
        #pragma unroll
        for (int j = 0; j < 13; j++) {
            unsigned long long w2 = bcast2(sW[k*104 + o0 + j]);
            fma2(acc[0][j], a0, w2); fma2(acc[1][j], a1, w2);
        }
    }
    for (int pass = 0; pass < 4; pass++) {
        __syncthreads();
        if (ng >= pass*8 && ng < pass*8 + 8) {
            int rbase = n0 - pass*32;
            #pragma unroll
            for (int p = 0; p < 2; p++) {
                #pragma unroll
                for (int j = 0; j < 13; j++) {
                    int oo = o0 + j;
                    float bv = sbias[oo];
                    int src = (oo >= 52);
                    int ol = src ? oo - 52 : oo;
                    int off = (src ? 56 : 0) + (ol / 26) * 28 + (ol % 26);
                    float2 v = *reinterpret_cast<float2*>(&acc[p][j]);
                    stage[(rbase + 2*p)*112 + off]     = v.x + bv;
                    stage[(rbase + 2*p + 1)*112 + off] = v.y + bv;
                }
            }
        }
        __syncthreads();
        float4* dst = reinterpret_cast<float4*>(g_DS + ((size_t)nb + pass*32)*DSST);
        const float4* srcp = reinterpret_cast<const float4*>(stage);
        for (int i = tid; i < 896; i += 256) dst[i] = srcp[i];
    }
    if (tid < 128) {
        float4 z = make_float4(0.f, 0.f, 0.f, 0.f);
        float4* zp = reinterpret_cast<float4*>(g_acc + (size_t)(nb + tid)*ACST);
        #pragma unroll
        for (int q = 0; q < 7; q++) zp[q] = z;
    }
}

// ---- layer-2 per-edge gate + message + scatter; 2 threads per edge
__device__ __forceinline__ void edge_chunk(const float* Dp, const float* Sp,
        const float* Eb, float* ap, int o) {
    float4 df = *reinterpret_cast<const float4*>(Dp + o);
    float4 ds = *reinterpret_cast<const float4*>(Dp + 28 + o);
    float4 sf = *reinterpret_cast<const float4*>(Sp + o);
    float4 ss = *reinterpret_cast<const float4*>(Sp + 28 + o);
    float4 ef = __ldcs(reinterpret_cast<const float4*>(Eb + o));
    float4 es = __ldcs(reinterpret_cast<const float4*>(Eb + 28 + o));
    float m0, m1, m2, m3;
    msg4(df, ds, sf, ss, ef, es, m0, m1, m2, m3);
    redv4(ap + o, m0, m1, m2, m3);
}

__global__ __launch_bounds__(512) void k_edge(const int* __restrict__ ei) {
    int t = blockIdx.x*512 + threadIdx.x;
    int e = t >> 1, half = t & 1;
    int s = ei[e], d = ei[ET + e];
    const float* Dp = g_DS + (size_t)d*DSST;
    const float* Sp = g_DS + (size_t)s*DSST + 56;
    const float* Eb = g_Ep + (size_t)e*EPST;
    float* ap = g_acc + (size_t)d*ACST;
    if (half == 0) {
        edge_chunk(Dp, Sp, Eb, ap, 0);
        edge_chunk(Dp, Sp, Eb, ap, 4);
        edge_chunk(Dp, Sp, Eb, ap, 8);
        edge_chunk(Dp, Sp, Eb, ap, 12);
    } else {
        edge_chunk(Dp, Sp, Eb, ap, 16);
        edge_chunk(Dp, Sp, Eb, ap, 20);
        edge_chunk(Dp, Sp, Eb, ap, 24);   // pad lanes land in unread acc pads
    }
}

__global__ void k_finalize(const float* __restrict__ xin, int layer) {
    int n = blockIdx.x*256 + threadIdx.x;
    const float* prev = layer ? g_h1 : xin;
    float* outp = layer ? g_h2 : g_h1;
    const float* ac = g_acc + (size_t)n*ACST;
    #pragma unroll
    for (int j = 0; j < 26; j++)
        outp[(size_t)n*26 + j] = tanhf(prev[(size_t)n*26 + j] + ac[j]);
}

__global__ __launch_bounds__(256) void k_softmax(const float* __restrict__ ic) {
    __shared__ float red[256];
    int g = blockIdx.x, t = threadIdx.x;
    size_t base = (size_t)g * NPG;
    float v0 = ic[base + t], v1 = ic[base + 256 + t];
    red[t] = fmaxf(v0, v1); __syncthreads();
    for (int st = 128; st > 0; st >>= 1) {
        if (t < st) red[t] = fmaxf(red[t], red[t + st]);
        __syncthreads();
    }
    float m = red[0]; __syncthreads();
    float e0 = __expf(v0 - m), e1 = __expf(v1 - m);
    red[t] = e0 + e1; __syncthreads();
    for (int st = 128; st > 0; st >>= 1) {
        if (t < st) red[t] += red[t + st];
        __syncthreads();
    }
    float inv = 1.f / red[0];
    g_sm[base + t] = e0 * inv;
    g_sm[base + 256 + t] = e1 * inv;
}

__global__ __launch_bounds__(256) void k_sortpool(const float* __restrict__ Wc1,
        const float* __restrict__ bc1, const float* __restrict__ Wc2,
        const float* __restrict__ bc2) {
    __shared__ float sv[512];
    __shared__ unsigned short si[512];
    __shared__ float pf[128*53];
    __shared__ float m16[16*64];
    __shared__ float swc1[16*53];
    __shared__ float swc2[2560];
    __shared__ float sb1[16], sb2[32];
    int g = blockIdx.x, t = threadIdx.x;
    size_t nb = (size_t)g * NPG;
    sv[t] = g_sm[nb + t];           si[t] = (unsigned short)t;
    sv[t+256] = g_sm[nb + 256 + t]; si[t+256] = (unsigned short)(t + 256);
    for (int i = t; i < 16*53; i += 256) swc1[i] = Wc1[i];
    for (int i = t; i < 2560;  i += 256) swc2[i] = Wc2[i];
    if (t < 16) sb1[t] = bc1[t];
    if (t < 32) sb2[t] = bc2[t];
    __syncthreads();
    for (int size = 2; size <= 512; size <<= 1) {
        for (int stride = size >> 1; stride > 0; stride >>= 1) {
            int q = t / stride, r = t - q*stride;
            int i = q*2*stride + r, j = i + stride;
            bool dir = ((i & size) == 0);
            float av = sv[i], bv = sv[j];
            int ai = si[i], bi = si[j];
            bool before = (av > bv) || (av == bv && ai < bi);
            if (dir ? !before : before) {
                sv[i] = bv; sv[j] = av;
                si[i] = (unsigned short)bi; si[j] = (unsigned short)ai;
            }
            __syncthreads();
        }
    }
    for (int i = t; i < 128*53; i += 256) {
        int k = i / 53, l = i - k*53;
        int node = (int)nb + (int)si[k];
        float v;
        if (l < 26)      v = g_h1[(size_t)node*26 + l];
        else if (l < 52) v = g_h2[(size_t)node*26 + l - 26];
        else             v = sv[k];
        pf[i] = v;
    }
    __syncthreads();
    for (int task = t; task < 1024; task += 256) {
        int c = task & 15, j = task >> 4;
        const float* w  = swc1 + c*53;
        const float* p0 = pf + (2*j)*53;
        const float* p1 = p0 + 53;
        float a = sb1[c], b = sb1[c];
        #pragma unroll 13
        for (int l = 0; l < 53; l++) { a += w[l]*p0[l]; b += w[l]*p1[l]; }
        a = fmaxf(a, 0.f); b = fmaxf(b, 0.f);
        m16[c*64 + j] = fmaxf(a, b);
    }
    __syncthreads();
    for (int task = t; task < 1920; task += 256) {
        int oc = task / 60, p = task - oc*60;
        float acc = sb2[oc];
        #pragma unroll 4
        for (int ic2 = 0; ic2 < 16; ic2++) {
            const float* w  = swc2 + (oc*16 + ic2)*5;
            const float* mm = m16 + ic2*64 + p;
            #pragma unroll
            for (int u = 0; u < 5; u++) acc += w[u]*mm[u];
        }
        g_c2[g*1920 + task] = fmaxf(acc, 0.f);
    }
}

__global__ void k_transW0(const float* __restrict__ W0) {
    int i = blockIdx.x*256 + threadIdx.x;
    int k = i >> 9, o = i & 511;
    g_W0T[i] = W0[o*1920 + k];
}
__global__ void k_transW1(const float* __restrict__ W1) {
    int i = blockIdx.x*256 + threadIdx.x;
    int k = i >> 8, o = i & 255;
    g_W1T[i] = W1[o*512 + k];
}

__global__ __launch_bounds__(256) void k_dense0(const float* __restrict__ b0) {
    __shared__ float sA[4*1920];
    int t = threadIdx.x, gb = blockIdx.x*4;
    for (int i = t; i < 4*1920; i += 256) sA[i] = g_c2[gb*1920 + i];
    __syncthreads();
    float bb0 = b0[t], bb1 = b0[t + 256];
    float acc0[4], acc1[4];
    #pragma unroll
    for (int g2 = 0; g2 < 4; g2++) { acc0[g2] = bb0; acc1[g2] = bb1; }
    for (int k = 0; k < 1920; k++) {
        float w0 = g_W0T[k*512 + t];
        float w1 = g_W0T[k*512 + t + 256];
        #pragma unroll
        for (int g2 = 0; g2 < 4; g2++) {
            float a = sA[g2*1920 + k];
            acc0[g2] += a*w0; acc1[g2] += a*w1;
        }
    }
    #pragma unroll
    for (int g2 = 0; g2 < 4; g2++) {
        g_d0[(gb + g2)*512 + t]       = fmaxf(acc0[g2], 0.f);
        g_d0[(gb + g2)*512 + t + 256] = fmaxf(acc1[g2], 0.f);
    }
}

__global__ __launch_bounds__(256) void k_dense12(const float* __restrict__ b1,
        const float* __restrict__ W2, const float* __restrict__ b2,
        float* __restrict__ out) {
    __shared__ float sd[512];
    __shared__ float red[256];
    int g = blockIdx.x, t = threadIdx.x;
    sd[t] = g_d0[g*512 + t]; sd[t+256] = g_d0[g*512 + 256 + t];
    __syncthreads();
    float acc = b1[t];
    #pragma unroll 8
    for (int k = 0; k < 512; k++) acc += sd[k] * g_W1T[k*256 + t];
    red[t] = fmaxf(acc, 0.f) * W2[t];
    __syncthreads();
    for (int st = 128; st > 0; st >>= 1) {
        if (t < st) red[t] += red[t + st];
        __syncthreads();
    }
    if (t == 0) out[g] = red[0] + b2[0];
}

extern "C" void kernel_launch(void* const* d_in, const int* in_sizes, int n_in,
                              void* d_out, int out_size) {
    const float* x   = (const float*)d_in[0];
    const float* ea  = (const float*)d_in[1];
    const float* ic  = (const float*)d_in[2];
    const float* Wf1 = (const float*)d_in[3];
    const float* bf1 = (const float*)d_in[4];
    const float* Ws1 = (const float*)d_in[5];
    const float* bs1 = (const float*)d_in[6];
    const float* Wf2 = (const float*)d_in[7];
    const float* bf2 = (const float*)d_in[8];
    const float* Ws2 = (const float*)d_in[9];
    const float* bs2 = (const float*)d_in[10];
    const float* Wc1 = (const float*)d_in[11];
    const float* bc1 = (const float*)d_in[12];
    const float* Wc2 = (const float*)d_in[13];
    const float* bc2 = (const float*)d_in[14];
    const float* W0  = (const float*)d_in[15];
    const float* b0  = (const float*)d_in[16];
    const float* W1  = (const float*)d_in[17];
    const float* b1  = (const float*)d_in[18];
    const float* W2  = (const float*)d_in[19];
    const float* b2  = (const float*)d_in[20];
    const int*   ei  = (const int*)d_in[21];
    float* out = (float*)d_out;

    // k_eproj_fused placed 4th so the ncu slot profiles it
    k_transW0<<<3840, 256>>>(W0);
    k_transW1<<<512, 256>>>(W1);
    k_nodeproj<<<NT/128, 256>>>(x, 0, Wf1, Ws1, bf1, bs1);
    k_eproj_fused<<<ET/128, 256>>>(ea, Wf1, Ws1, Wf2, Ws2, ei);
    k_finalize<<<NT/256, 256>>>(x, 0);

    k_nodeproj<<<NT/128, 256>>>(x, 1, Wf2, Ws2, bf2, bs2);
    k_edge<<<ET/256, 512>>>(ei);
    k_finalize<<<NT/256, 256>>>(x, 1);

    k_softmax<<<GN, 256>>>(ic);
    k_sortpool<<<GN, 256>>>(Wc1, bc1, Wc2, bc2);
    k_dense0<<<GN/4, 256>>>(b0);
    k_dense12<<<GN, 256>>>(b1, W2, b2, out);
}

// round 8
// speedup vs baseline: 1.5275x; 1.0305x over previous
#include <cuda_runtime.h>
#include <math.h>

#define GN   256
#define NPG  512
#define NT   (GN*NPG)
#define ET   1048576
#define SAST 130

#define DSST 112     // g_DS row: [D-f|pad|D-s|pad|S-f|pad|S-s|pad] (28 apart)
#define EPST 56      // g_Ep row (L2 only): [f 0..25|pad|s 28..53|pad]
#define ACST 28

// dynamic smem layout for k_eproj_fused
#define EP_SA_OFF    0        // 52*130 floats = 27040B
#define EP_SW_OFF    27040    // 52*56 float2  = 23296B
#define EP_STAGE_OFF 0        // 128*112 floats = 57344B (overlays sA/sW post-mainloop)
#define EP_SEDGE_OFF 57344    // 256 ints
#define EP_SMEM_DYN  58368

__device__ float g_Ep[(size_t)ET*EPST];
__device__ float g_DS[(size_t)NT*DSST];
__device__ float g_acc[(size_t)NT*ACST];
__device__ float g_h1[(size_t)NT*26];
__device__ float g_h2[(size_t)NT*26];
__device__ float g_sm[NT];
__device__ float g_c2[GN*1920];
__device__ float g_d0[GN*512];
__device__ float g_W0T[1920*512];
__device__ float g_W1T[512*256];

__device__ __forceinline__ void fma2(unsigned long long& d, unsigned long long a,
                                     unsigned long long b) {
    asm("fma.rn.f32x2 %0, %1, %2, %0;" : "+l"(d) : "l"(a), "l"(b));
}
__device__ __forceinline__ unsigned long long bcast2(float w) {
    unsigned long long r; unsigned wi = __float_as_uint(w);
    asm("mov.b64 %0, {%1, %1};" : "=l"(r) : "r"(wi));
    return r;
}
__device__ __forceinline__ void redv4(float* p, float a, float b, float c, float d) {
    asm volatile("red.global.add.v4.f32 [%0], {%1,%2,%3,%4};"
                 :: "l"(p), "f"(a), "f"(b), "f"(c), "f"(d) : "memory");
}

__device__ __forceinline__ void msg4(const float4 df, const float4 ds,
        const float4 sf, const float4 ss, const float4 ef, const float4 es,
        float& m0, float& m1, float& m2, float& m3) {
    float f0 = df.x+sf.x+ef.x, f1 = df.y+sf.y+ef.y;
    float f2 = df.z+sf.z+ef.z, f3 = df.w+sf.w+ef.w;
    float g0 = ds.x+ss.x+es.x, g1 = ds.y+ss.y+es.y;
    float g2 = ds.z+ss.z+es.z, g3 = ds.w+ss.w+es.w;
    m0 = (1.f/(1.f+__expf(-f0))) * ((g0>20.f)?g0:__logf(1.f+__expf(g0)));
    m1 = (1.f/(1.f+__expf(-f1))) * ((g1>20.f)?g1:__logf(1.f+__expf(g1)));
    m2 = (1.f/(1.f+__expf(-f2))) * ((g2>20.f)?g2:__logf(1.f+__expf(g2)));
    m3 = (1.f/(1.f+__expf(-f3))) * ((g3>20.f)?g3:__logf(1.f+__expf(g3)));
}

// ---- fused Eproj GEMM (both layers) + layer-1 combine; out-pair f32x2 tiling
__global__ __launch_bounds__(256) void k_eproj_fused(const float* __restrict__ ea,
        const float* __restrict__ Wf1, const float* __restrict__ Ws1,
        const float* __restrict__ Wf2, const float* __restrict__ Ws2,
        const int* __restrict__ ei) {
    extern __shared__ __align__(16) char dyn[];
    float* sA = (float*)(dyn + EP_SA_OFF);        // [k][edge], 52 x 130
    float2* sW2 = (float2*)(dyn + EP_SW_OFF);     // [k][slot], 52 x 56 weight pairs
    float* stage = (float*)(dyn + EP_STAGE_OFF);  // 128 x 112 (post-mainloop)
    int* sedge = (int*)(dyn + EP_SEDGE_OFF);      // 128 x {src,dst}
    int tid = threadIdx.x, eb = blockIdx.x * 128;

    for (int i = tid; i < 128*52; i += 256) {
        int e = i / 52, k = i - e*52;
        sA[k*SAST + e] = ea[(size_t)(eb + e)*52 + k];
    }
    // weight pairs: slot s (0..55): seg=s/14 selects matrix, idx=s%14; idx==13 is pad
    for (int i = tid; i < 52*56; i += 256) {
        int k = i / 56, s = i - k*56;
        int seg = s / 14, idx = s - seg*14;
        float2 w = make_float2(0.f, 0.f);
        if (idx < 13) {
            const float* W = (seg == 0) ? Wf1 : (seg == 1) ? Ws1 : (seg == 2) ? Wf2 : Ws2;
            int r = idx * 2;
            w.x = W[r*104 + 52 + k];
            w.y = W[(r + 1)*104 + 52 + k];
        }
        sW2[k*56 + s] = w;
    }
    if (tid < 128) {
        sedge[tid*2]     = ei[eb + tid];
        sedge[tid*2 + 1] = ei[ET + eb + tid];
    }
    __syncthreads();

    int og = tid & 7, eg = tid >> 3;
    int s0 = og * 7, e0 = eg * 4;                 // 7 pair-slots x 4 edges
    unsigned long long acc[4][7];
    #pragma unroll
    for (int p = 0; p < 4; p++)
        #pragma unroll
        for (int j = 0; j < 7; j++) acc[p][j] = 0ull;

    #pragma unroll 4
    for (int k = 0; k < 52; k++) {
        const float* ar = sA + k*SAST + e0;
        unsigned long long A0 = bcast2(ar[0]), A1 = bcast2(ar[1]);
        unsigned long long A2 = bcast2(ar[2]), A3 = bcast2(ar[3]);
        const unsigned long long* wp =
            reinterpret_cast<const unsigned long long*>(sW2 + k*56 + s0);
        #pragma unroll
        for (int j = 0; j < 7; j++) {
            unsigned long long w = wp[j];
            fma2(acc[0][j], A0, w); fma2(acc[1][j], A1, w);
            fma2(acc[2][j], A2, w); fma2(acc[3][j], A3, w);
        }
    }
    __syncthreads();   // mainloop done reading sA/sW before stage overlays them

    // stage: edge-major padded rows of 112 floats (56 pairs)
    float2* stage2 = (float2*)stage;
    #pragma unroll
    for (int p = 0; p < 4; p++)
        #pragma unroll
        for (int j = 0; j < 7; j++)
            stage2[(e0 + p)*56 + s0 + j] = *reinterpret_cast<float2*>(&acc[p][j]);
    __syncthreads();

    // flush layer-2 half (floats 56..111 of each staged row), coalesced
    {
        float4* dst = reinterpret_cast<float4*>(g_Ep + (size_t)eb*EPST);
        for (int i = tid; i < 1792; i += 256) {
            int e = i / 14, q = i - e*14;
            dst[(size_t)e*14 + q] =
                *reinterpret_cast<const float4*>(stage + e*112 + 56 + q*4);
        }
    }
    // layer-1 combine: 128 edges x 7 chunks
    for (int i = tid; i < 896; i += 256) {
        int el = i / 7, c = i - el*7, o = c*4;
        int s = sedge[el*2], d = sedge[el*2 + 1];
        const float* Dp = g_DS + (size_t)d*DSST;
        const float* Sp = g_DS + (size_t)s*DSST + 56;
        const float* Eb = stage + el*112;
        float4 df = *reinterpret_cast<const float4*>(Dp + o);
        float4 ds = *reinterpret_cast<const float4*>(Dp + 28 + o);
        float4 sf = *reinterpret_cast<const float4*>(Sp + o);
        float4 ss = *reinterpret_cast<const float4*>(Sp + 28 + o);
        float4 ef = *reinterpret_cast<const float4*>(Eb + o);
        float4 es = *reinterpret_cast<const float4*>(Eb + 28 + o);
        float m0, m1, m2, m3;
        msg4(df, ds, sf, ss, ef, es, m0, m1, m2, m3);
        redv4(g_acc + (size_t)d*ACST + o, m0, m1, m2, m3);
    }
}

// ---- node gate terms GEMM -> g_DS, staged coalesced stores; zero acc
__global__ __launch_bounds__(256) void k_nodeproj(const float* __restrict__ xin,
        int layer, const float* __restrict__ Wf, const float* __restrict__ Ws,
        const float* __restrict__ bf, const float* __restrict__ bs) {
    __shared__ __align__(16) char s_raw[39104];
    float* sA    = (float*)s_raw;
    float* sW    = (float*)(s_raw + 13520);
    float* sbias = (float*)(s_raw + 24336);
    float* stage = (float*)(s_raw + 24752);
    int tid = threadIdx.x, nb = blockIdx.x * 128;
    const float* h = layer ? g_h1 : xin;
    for (int i = tid; i < 128*26; i += 256) {
        int n = i / 26, k = i - n*26;
        sA[k*SAST + n] = h[(size_t)(nb + n)*26 + k];
    }
    for (int i = tid; i < 26*104; i += 256) {
        int k = i / 104, o = i - k*104;
        int half = (o < 52) ? 0 : 26;
        int oo = (o < 52) ? o : o - 52;
        const float* W = (oo < 26) ? Wf : Ws;
        int r = (oo < 26) ? oo : oo - 26;
        sW[i] = W[r*104 + half + k];
    }
    if (tid < 104) sbias[tid] = (tid < 26) ? bf[tid] : (tid < 52 ? bs[tid-26] : 0.f);
    __syncthreads();
    int og = tid & 7, ng = tid >> 3;
    int o0 = og * 13, n0 = ng * 4;
    unsigned long long acc[2][13];
    #pragma unroll
    for (int p = 0; p < 2; p++)
        #pragma unroll
        for (int j = 0; j < 13; j++) acc[p][j] = 0ull;
    #pragma unroll 2
    for (int k = 0; k < 26; k++) {
        const unsigned long long* ap =
            reinterpret_cast<const unsigned long long*>(sA + k*SAST + n0);
        unsigned long long a0 = ap[0], a1 = ap[1];
        #pragma unroll
        for (int j = 0; j < 13; j++) {
            unsigned long long w2 = bcast2(sW[k*104 + o0 + j]);
            fma2(acc[0][j], a0, w2); fma2(acc[1][j], a1, w2);
        }
    }
    for (int pass = 0; pass < 4; pass++) {
        __syncthreads();
        if (ng >= pass*8 && ng < pass*8 + 8) {
            int rbase = n0 - pass*32;
            #pragma unroll
            for (int p = 0; p < 2; p++) {
                #pragma unroll
                for (int j = 0; j < 13; j++) {
                    int oo = o0 + j;
                    float bv = sbias[oo];
                    int src = (oo >= 52);
                    int ol = src ? oo - 52 : oo;
                    int off = (src ? 56 : 0) + (ol / 26) * 28 + (ol % 26);
                    float2 v = *reinterpret_cast<float2*>(&acc[p][j]);
                    stage[(rbase + 2*p)*112 + off]     = v.x + bv;
                    stage[(rbase + 2*p + 1)*112 + off] = v.y + bv;
                }
            }
        }
        __syncthreads();
        float4* dst = reinterpret_cast<float4*>(g_DS + ((size_t)nb + pass*32)*DSST);
        const float4* srcp = reinterpret_cast<const float4*>(stage);
        for (int i = tid; i < 896; i += 256) dst[i] = srcp[i];
    }
    if (tid < 128) {
        float4 z = make_float4(0.f, 0.f, 0.f, 0.f);
        float4* zp = reinterpret_cast<float4*>(g_acc + (size_t)(nb + tid)*ACST);
        #pragma unroll
        for (int q = 0; q < 7; q++) zp[q] = z;
    }
}

// ---- layer-2 per-edge gate + message + scatter; 2 threads per edge
__device__ __forceinline__ void edge_chunk(const float* Dp, const float* Sp,
        const float* Eb, float* ap, int o) {
    float4 df = *reinterpret_cast<const float4*>(Dp + o);
    float4 ds = *reinterpret_cast<const float4*>(Dp + 28 + o);
    float4 sf = *reinterpret_cast<const float4*>(Sp + o);
    float4 ss = *reinterpret_cast<const float4*>(Sp + 28 + o);
    float4 ef = __ldcs(reinterpret_cast<const float4*>(Eb + o));
    float4 es = __ldcs(reinterpret_cast<const float4*>(Eb + 28 + o));
    float m0, m1, m2, m3;
    msg4(df, ds, sf, ss, ef, es, m0, m1, m2, m3);
    redv4(ap + o, m0, m1, m2, m3);
}

__global__ __launch_bounds__(512) void k_edge(const int* __restrict__ ei) {
    int t = blockIdx.x*512 + threadIdx.x;
    int e = t >> 1, half = t & 1;
    int s = ei[e], d = ei[ET + e];
    const float* Dp = g_DS + (size_t)d*DSST;
    const float* Sp = g_DS + (size_t)s*DSST + 56;
    const float* Eb = g_Ep + (size_t)e*EPST;
    float* ap = g_acc + (size_t)d*ACST;
    if (half == 0) {
        edge_chunk(Dp, Sp, Eb, ap, 0);
        edge_chunk(Dp, Sp, Eb, ap, 4);
        edge_chunk(Dp, Sp, Eb, ap, 8);
        edge_chunk(Dp, Sp, Eb, ap, 12);
    } else {
        edge_chunk(Dp, Sp, Eb, ap, 16);
        edge_chunk(Dp, Sp, Eb, ap, 20);
        edge_chunk(Dp, Sp, Eb, ap, 24);
    }
}

__global__ void k_finalize(const float* __restrict__ xin, int layer) {
    int n = blockIdx.x*256 + threadIdx.x;
    const float* prev = layer ? g_h1 : xin;
    float* outp = layer ? g_h2 : g_h1;
    const float* ac = g_acc + (size_t)n*ACST;
    #pragma unroll
    for (int j = 0; j < 26; j++)
        outp[(size_t)n*26 + j] = tanhf(prev[(size_t)n*26 + j] + ac[j]);
}

__global__ __launch_bounds__(256) void k_softmax(const float* __restrict__ ic) {
    __shared__ float red[256];
    int g = blockIdx.x, t = threadIdx.x;
    size_t base = (size_t)g * NPG;
    float v0 = ic[base + t], v1 = ic[base + 256 + t];
    red[t] = fmaxf(v0, v1); __syncthreads();
    for (int st = 128; st > 0; st >>= 1) {
        if (t < st) red[t] = fmaxf(red[t], red[t + st]);
        __syncthreads();
    }
    float m = red[0]; __syncthreads();
    float e0 = __expf(v0 - m), e1 = __expf(v1 - m);
    red[t] = e0 + e1; __syncthreads();
    for (int st = 128; st > 0; st >>= 1) {
        if (t < st) red[t] += red[t + st];
        __syncthreads();
    }
    float inv = 1.f / red[0];
    g_sm[base + t] = e0 * inv;
    g_sm[base + 256 + t] = e1 * inv;
}

__global__ __launch_bounds__(256) void k_sortpool(const float* __restrict__ Wc1,
        const float* __restrict__ bc1, const float* __restrict__ Wc2,
        const float* __restrict__ bc2) {
    __shared__ float sv[512];
    __shared__ unsigned short si[512];
    __shared__ float pf[128*53];
    __shared__ float m16[16*64];
    __shared__ float swc1[16*53];
    __shared__ float swc2[2560];
    __shared__ float sb1[16], sb2[32];
    int g = blockIdx.x, t = threadIdx.x;
    size_t nb = (size_t)g * NPG;
    sv[t] = g_sm[nb + t];           si[t] = (unsigned short)t;
    sv[t+256] = g_sm[nb + 256 + t]; si[t+256] = (unsigned short)(t + 256);
    for (int i = t; i < 16*53; i += 256) swc1[i] = Wc1[i];
    for (int i = t; i < 2560;  i += 256) swc2[i] = Wc2[i];
    if (t < 16) sb1[t] = bc1[t];
    if (t < 32) sb2[t] = bc2[t];
    __syncthreads();
    for (int size = 2; size <= 512; size <<= 1) {
        for (int stride = size >> 1; stride > 0; stride >>= 1) {
            int q = t / stride, r = t - q*stride;
            int i = q*2*stride + r, j = i + stride;
            bool dir = ((i & size) == 0);
            float av = sv[i], bv = sv[j];
            int ai = si[i], bi = si[j];
            bool before = (av > bv) || (av == bv && ai < bi);
            if (dir ? !before : before) {
                sv[i] = bv; sv[j] = av;
                si[i] = (unsigned short)bi; si[j] = (unsigned short)ai;
            }
            __syncthreads();
        }
    }
    for (int i = t; i < 128*53; i += 256) {
        int k = i / 53, l = i - k*53;
        int node = (int)nb + (int)si[k];
        float v;
        if (l < 26)      v = g_h1[(size_t)node*26 + l];
        else if (l < 52) v = g_h2[(size_t)node*26 + l - 26];
        else             v = sv[k];
        pf[i] = v;
    }
    __syncthreads();
    for (int task = t; task < 1024; task += 256) {
        int c = task & 15, j = task >> 4;
        const float* w  = swc1 + c*53;
        const float* p0 = pf + (2*j)*53;
        const float* p1 = p0 + 53;
        float a = sb1[c], b = sb1[c];
        #pragma unroll 13
        for (int l = 0; l < 53; l++) { a += w[l]*p0[l]; b += w[l]*p1[l]; }
        a = fmaxf(a, 0.f); b = fmaxf(b, 0.f);
        m16[c*64 + j] = fmaxf(a, b);
    }
    __syncthreads();
    for (int task = t; task < 1920; task += 256) {
        int oc = task / 60, p = task - oc*60;
        float acc = sb2[oc];
        #pragma unroll 4
        for (int ic2 = 0; ic2 < 16; ic2++) {
            const float* w  = swc2 + (oc*16 + ic2)*5;
            const float* mm = m16 + ic2*64 + p;
            #pragma unroll
            for (int u = 0; u < 5; u++) acc += w[u]*mm[u];
        }
        g_c2[g*1920 + task] = fmaxf(acc, 0.f);
    }
}

__global__ void k_transW0(const float* __restrict__ W0) {
    int i = blockIdx.x*256 + threadIdx.x;
    int k = i >> 9, o = i & 511;
    g_W0T[i] = W0[o*1920 + k];
}
__global__ void k_transW1(const float* __restrict__ W1) {
    int i = blockIdx.x*256 + threadIdx.x;
    int k = i >> 8, o = i & 255;
    g_W1T[i] = W1[o*512 + k];
}

__global__ __launch_bounds__(256) void k_dense0(const float* __restrict__ b0) {
    __shared__ float sA[4*1920];
    int t = threadIdx.x, gb = blockIdx.x*4;
    for (int i = t; i < 4*1920; i += 256) sA[i] = g_c2[gb*1920 + i];
    __syncthreads();
    float bb0 = b0[t], bb1 = b0[t + 256];
    float acc0[4], acc1[4];
    #pragma unroll
    for (int g2 = 0; g2 < 4; g2++) { acc0[g2] = bb0; acc1[g2] = bb1; }
    for (int k = 0; k < 1920; k++) {
        float w0 = g_W0T[k*512 + t];
        float w1 = g_W0T[k*512 + t + 256];
        #pragma unroll
        for (int g2 = 0; g2 < 4; g2++) {
            float a = sA[g2*1920 + k];
            acc0[g2] += a*w0; acc1[g2] += a*w1;
        }
    }
    #pragma unroll
    for (int g2 = 0; g2 < 4; g2++) {
        g_d0[(gb + g2)*512 + t]       = fmaxf(acc0[g2], 0.f);
        g_d0[(gb + g2)*512 + t + 256] = fmaxf(acc1[g2], 0.f);
    }
}

__global__ __launch_bounds__(256) void k_dense12(const float* __restrict__ b1,
        const float* __restrict__ W2, const float* __restrict__ b2,
        float* __restrict__ out) {
    __shared__ float sd[512];
    __shared__ float red[256];
    int g = blockIdx.x, t = threadIdx.x;
    sd[t] = g_d0[g*512 + t]; sd[t+256] = g_d0[g*512 + 256 + t];
    __syncthreads();
    float acc = b1[t];
    #pragma unroll 8
    for (int k = 0; k < 512; k++) acc += sd[k] * g_W1T[k*256 + t];
    red[t] = fmaxf(acc, 0.f) * W2[t];
    __syncthreads();
    for (int st = 128; st > 0; st >>= 1) {
        if (t < st) red[t] += red[t + st];
        __syncthreads();
    }
    if (t == 0) out[g] = red[0] + b2[0];
}

extern "C" void kernel_launch(void* const* d_in, const int* in_sizes, int n_in,
                              void* d_out, int out_size) {
    const float* x   = (const float*)d_in[0];
    const float* ea  = (const float*)d_in[1];
    const float* ic  = (const float*)d_in[2];
    const float* Wf1 = (const float*)d_in[3];
    const float* bf1 = (const float*)d_in[4];
    const float* Ws1 = (const float*)d_in[5];
    const float* bs1 = (const float*)d_in[6];
    const float* Wf2 = (const float*)d_in[7];
    const float* bf2 = (const float*)d_in[8];
    const float* Ws2 = (const float*)d_in[9];
    const float* bs2 = (const float*)d_in[10];
    const float* Wc1 = (const float*)d_in[11];
    const float* bc1 = (const float*)d_in[12];
    const float* Wc2 = (const float*)d_in[13];
    const float* bc2 = (const float*)d_in[14];
    const float* W0  = (const float*)d_in[15];
    const float* b0  = (const float*)d_in[16];
    const float* W1  = (const float*)d_in[17];
    const float* b1  = (const float*)d_in[18];
    const float* W2  = (const float*)d_in[19];
    const float* b2  = (const float*)d_in[20];
    const int*   ei  = (const int*)d_in[21];
    float* out = (float*)d_out;

    cudaFuncSetAttribute(k_eproj_fused,
                         cudaFuncAttributeMaxDynamicSharedMemorySize, EP_SMEM_DYN);

    // k_eproj_fused placed 4th so the ncu slot profiles it
    k_transW0<<<3840, 256>>>(W0);
    k_transW1<<<512, 256>>>(W1);
    k_nodeproj<<<NT/128, 256>>>(x, 0, Wf1, Ws1, bf1, bs1);
    k_eproj_fused<<<ET/128, 256, EP_SMEM_DYN>>>(ea, Wf1, Ws1, Wf2, Ws2, ei);
    k_finalize<<<NT/256, 256>>>(x, 0);

    k_nodeproj<<<NT/128, 256>>>(x, 1, Wf2, Ws2, bf2, bs2);
    k_edge<<<ET/256, 512>>>(ei);
    k_finalize<<<NT/256, 256>>>(x, 1);

    k_softmax<<<GN, 256>>>(ic);
    k_sortpool<<<GN, 256>>>(Wc1, bc1, Wc2, bc2);
    k_dense0<<<GN/4, 256>>>(b0);
    k_dense12<<<GN, 256>>>(b1, W2, b2, out);
}